// round 2
// baseline (speedup 1.0000x reference)
#include <cuda_runtime.h>

// ---------------------------------------------------------------------------
// VQ-VAE forward, sm_100a.  fp32 direct convs with packed fma.rn.f32x2.
// Output layout: [x_recon | z_e | z_q | idx(as float)], fp32.
// ---------------------------------------------------------------------------

#define NBATCH 16
typedef unsigned long long ull;

__device__ __forceinline__ ull pk2(float lo, float hi) {
    ull r; asm("mov.b64 %0,{%1,%2};" : "=l"(r) : "f"(lo), "f"(hi)); return r;
}
__device__ __forceinline__ void upk2(ull v, float& lo, float& hi) {
    asm("mov.b64 {%0,%1},%2;" : "=f"(lo), "=f"(hi) : "l"(v));
}
__device__ __forceinline__ ull ffma2(ull a, ull b, ull c) {
    ull d; asm("fma.rn.f32x2 %0,%1,%2,%3;" : "=l"(d) : "l"(a), "l"(b), "l"(c));
    return d;
}

// -------- scratch ----------------------------------------------------------
__device__ float g_h1[NBATCH * 128 * 128 * 128];
__device__ float g_h2[NBATCH * 256 * 64 * 64];
__device__ float g_g1[NBATCH * 256 * 64 * 64];
__device__ float g_g2[NBATCH * 128 * 128 * 128];  // also conv3 partial scratch
__device__ float g_ze[NBATCH * 64 * 32 * 32];
__device__ float g_zq[NBATCH * 64 * 32 * 32];
__device__ float g_if[16384];
__device__ float g_wt1[128 * 3 * 16];
__device__ float g_wt2[256 * 128 * 16];
__device__ float g_wt3[64 * 256 * 16];

// -------- weight transpose: OIHW -> [ic][oc][t] ----------------------------
__global__ void wtrans(const float* __restrict__ w, float* __restrict__ wo,
                       int Cout, int Cin) {
    int idx = blockIdx.x * 256 + threadIdx.x;
    int total = Cout * Cin * 16;
    if (idx < total) {
        int t = idx & 15;
        int rest = idx >> 4;
        int ic = rest % Cin;
        int oc = rest / Cin;
        wo[(ic * Cout + oc) * 16 + t] = w[idx];
    }
}

// -------- generic conv k4 s2 p1 (packed f32x2) -----------------------------
// Block: 64 oc x 16x16 spatial tile.  Thread: 8 oc x 8 cols (as 4 f32x2).
// Optional input-channel slab split (nSlab>1): partials to out+slab*partStride.
template <int CIN, bool RELU>
__global__ __launch_bounds__(256, 2)
void conv4s2(const float* __restrict__ in, const float* __restrict__ wt,
             const float* __restrict__ bias, float* __restrict__ out,
             int Cout, int Hin, int Win, int Hout, int Wout, int tilesX,
             int nSlab, int partStride) {
    __shared__ float ish[34 * 36];
    __shared__ ull wsh[64 * 16];

    const int tile = blockIdx.x;
    const int tx0 = (tile % tilesX) * 16;
    const int ty0 = (tile / tilesX) * 16;
    const int ocb = blockIdx.y * 64;
    const int bz  = blockIdx.z;
    const int b    = bz / nSlab;
    const int slab = bz - b * nSlab;

    const int tid = threadIdx.x;
    const int og  = tid >> 5;
    const int sp  = tid & 31;
    const int r   = sp >> 1;
    const int cb  = (sp & 1) * 8;

    ull acc[8][4];
#pragma unroll
    for (int o = 0; o < 8; o++) {
        float bv = bias ? bias[ocb + og * 8 + o] : 0.f;
        ull bp = pk2(bv, bv);
#pragma unroll
        for (int j = 0; j < 4; j++) acc[o][j] = bp;
    }

    const int iy0 = ty0 * 2 - 1, ix0 = tx0 * 2 - 1;
    const float* inB = in + ((size_t)b * (CIN * nSlab) + slab * CIN) * Hin * Win;
    const float* wtS = wt + (size_t)slab * CIN * Cout * 16;

    for (int ic = 0; ic < CIN; ic++) {
        const float* inC = inB + (size_t)ic * Hin * Win;
        for (int idx = tid; idx < 34 * 34; idx += 256) {
            int py = idx / 34, px = idx - py * 34;
            int iy = iy0 + py, ix = ix0 + px;
            float v = 0.f;
            if ((unsigned)iy < (unsigned)Hin && (unsigned)ix < (unsigned)Win)
                v = inC[iy * Win + ix];
            ish[py * 36 + px] = v;
        }
        const float* wC = wtS + (ic * Cout + ocb) * 16;
        for (int idx = tid; idx < 1024; idx += 256) {
            float w = wC[idx];
            wsh[idx] = pk2(w, w);
        }
        __syncthreads();

#pragma unroll
        for (int ky = 0; ky < 4; ky++) {
            const float* rp = &ish[(2 * r + ky) * 36 + 2 * cb];
            float4 v0 = *(const float4*)(rp);
            float4 v1 = *(const float4*)(rp + 4);
            float4 v2 = *(const float4*)(rp + 8);
            float4 v3 = *(const float4*)(rp + 12);
            float4 v4 = *(const float4*)(rp + 16);
            float riv[20] = {v0.x, v0.y, v0.z, v0.w, v1.x, v1.y, v1.z, v1.w,
                             v2.x, v2.y, v2.z, v2.w, v3.x, v3.y, v3.z, v3.w,
                             v4.x, v4.y, v4.z, v4.w};
#pragma unroll
            for (int kx = 0; kx < 4; kx++) {
                const int t = ky * 4 + kx;
                ull iv2[4];
#pragma unroll
                for (int jj = 0; jj < 4; jj++)
                    iv2[jj] = pk2(riv[kx + 4 * jj], riv[kx + 4 * jj + 2]);
#pragma unroll
                for (int o = 0; o < 8; o++) {
                    ull wv = wsh[(og * 8 + o) * 16 + t];
#pragma unroll
                    for (int jj = 0; jj < 4; jj++)
                        acc[o][jj] = ffma2(wv, iv2[jj], acc[o][jj]);
                }
            }
        }
        __syncthreads();
    }

    const int oy = ty0 + r;
    const int oxb = tx0 + cb;
    float* outS = out + (size_t)slab * partStride;
#pragma unroll
    for (int o = 0; o < 8; o++) {
        float* op = outS + (((size_t)b * Cout + ocb + og * 8 + o) * Hout + oy) * Wout + oxb;
        float t0, t1, t2, t3, t4, t5, t6, t7;
        upk2(acc[o][0], t0, t1);
        upk2(acc[o][1], t2, t3);
        upk2(acc[o][2], t4, t5);
        upk2(acc[o][3], t6, t7);
        if (RELU) {
            t0 = fmaxf(t0, 0.f); t1 = fmaxf(t1, 0.f); t2 = fmaxf(t2, 0.f);
            t3 = fmaxf(t3, 0.f); t4 = fmaxf(t4, 0.f); t5 = fmaxf(t5, 0.f);
            t6 = fmaxf(t6, 0.f); t7 = fmaxf(t7, 0.f);
        }
        *(float4*)op       = make_float4(t0, t1, t2, t3);
        *(float4*)(op + 4) = make_float4(t4, t5, t6, t7);
    }
}

// -------- conv3 slab reduction ---------------------------------------------
__global__ void addparts(const float* __restrict__ p, const float* __restrict__ bias,
                         float* __restrict__ ze) {
    const int S = NBATCH * 64 * 32 * 32;
    int i = blockIdx.x * 256 + threadIdx.x;
    float v = p[i] + p[i + S] + p[i + 2 * S] + p[i + 3 * S];
    ze[i] = v + bias[(i >> 10) & 63];
}

// -------- transposed conv k4 s2 p1 (gather, packed f32x2) ------------------
template <bool RELU>
__global__ __launch_bounds__(256, 2)
void dconv4s2(const float* __restrict__ in, const float* __restrict__ wt,
              const float* __restrict__ bias, float* __restrict__ out,
              int Cin, int Cout, int Hin, int Win, int tilesX) {
    const int Hout = Hin * 2, Wout = Win * 2;
    __shared__ ull wsh[4][64 * 16];
    __shared__ float ish[4][10 * 16];

    const int tile = blockIdx.x;
    const int ox0 = (tile % tilesX) * 16;
    const int oy0 = (tile / tilesX) * 16;
    const int ocb = blockIdx.y * 64;
    const int b   = blockIdx.z;

    const int tid = threadIdx.x;
    const int og  = tid >> 5;
    const int sp  = tid & 31;
    const int q   = sp >> 3;
    const int py  = q >> 1, px = q & 1;
    const int ry  = sp & 7;

    ull acc[8][4];
#pragma unroll
    for (int o = 0; o < 8; o++) {
        float bv = bias[ocb + og * 8 + o];
        ull bp = pk2(bv, bv);
#pragma unroll
        for (int j = 0; j < 4; j++) acc[o][j] = bp;
    }

    const int iy0 = oy0 >> 1, ix0 = ox0 >> 1;
    const int kp = 1 - py;
    const int kq = 1 - px;

    for (int ic0 = 0; ic0 < Cin; ic0 += 4) {
        for (int idx = tid; idx < 4 * 100; idx += 256) {
            int icc = idx / 100, p = idx - icc * 100;
            int piy = p / 10, pix = p - piy * 10;
            int iy = iy0 - 1 + piy, ix = ix0 - 1 + pix;
            float v = 0.f;
            if ((unsigned)iy < (unsigned)Hin && (unsigned)ix < (unsigned)Win)
                v = in[(((size_t)b * Cin + ic0 + icc) * Hin + iy) * Win + ix];
            ish[icc][piy * 16 + pix] = v;
        }
        for (int idx = tid; idx < 4 * 1024; idx += 256) {
            int icc = idx >> 10, rmd = idx & 1023;
            float w = wt[((ic0 + icc) * Cout + ocb) * 16 + rmd];
            wsh[icc][rmd] = pk2(w, w);
        }
        __syncthreads();

#pragma unroll
        for (int icc = 0; icc < 4; icc++) {
#pragma unroll
            for (int a = 0; a < 2; a++) {
                const int ky  = kp + 2 * a;
                const int liy = ry + 1 + py - a;
                const float* rp = &ish[icc][liy * 16];
                float4 u0 = *(const float4*)(rp);
                float4 u1 = *(const float4*)(rp + 4);
                float2 u2 = *(const float2*)(rp + 8);
                float riv[10] = {u0.x, u0.y, u0.z, u0.w,
                                 u1.x, u1.y, u1.z, u1.w, u2.x, u2.y};
#pragma unroll
                for (int c = 0; c < 2; c++) {
                    const int kx = kq + 2 * c;
                    const int cc = px - c + 1;
                    const int t  = ky * 4 + kx;
                    ull iv2[4];
#pragma unroll
                    for (int jj = 0; jj < 4; jj++)
                        iv2[jj] = pk2(riv[cc + 2 * jj], riv[cc + 2 * jj + 1]);
#pragma unroll
                    for (int o = 0; o < 8; o++) {
                        ull wv = wsh[icc][(og * 8 + o) * 16 + t];
#pragma unroll
                        for (int jj = 0; jj < 4; jj++)
                            acc[o][jj] = ffma2(wv, iv2[jj], acc[o][jj]);
                    }
                }
            }
        }
        __syncthreads();
    }

    const int oy = oy0 + 2 * ry + py;
#pragma unroll
    for (int o = 0; o < 8; o++) {
        float* op = out + (((size_t)b * Cout + ocb + og * 8 + o) * Hout + oy) * Wout + ox0 + px;
        float t0, t1;
#pragma unroll
        for (int jj = 0; jj < 4; jj++) {
            upk2(acc[o][jj], t0, t1);
            if (RELU) { t0 = fmaxf(t0, 0.f); t1 = fmaxf(t1, 0.f); }
            op[2 * (2 * jj)]     = t0;
            op[2 * (2 * jj + 1)] = t1;
        }
    }
}

// -------- final transposed conv: 128 -> 3, 128x128 -> 256x256 --------------
__global__ __launch_bounds__(128, 4)
void dconv3out(const float* __restrict__ in, const float* __restrict__ wt,
               const float* __restrict__ bias, float* __restrict__ out,
               int tilesX) {
    const int Cin = 128, Hin = 128, Win = 128, Hout = 256, Wout = 256;
    __shared__ float ish[4][18 * 19];
    __shared__ float wsh[4][3 * 16];

    const int tile = blockIdx.x;
    const int ox0 = (tile % tilesX) * 32;
    const int oy0 = (tile / tilesX) * 32;
    const int b   = blockIdx.y;

    const int tid = threadIdx.x;
    const int q   = tid >> 5;
    const int py  = q >> 1, px = q & 1;
    const int sp  = tid & 31;
    const int ry  = sp >> 1;
    const int ch  = (sp & 1) * 8;

    ull acc[3][4];
#pragma unroll
    for (int o = 0; o < 3; o++) {
        float bv = bias[o];
        ull bp = pk2(bv, bv);
#pragma unroll
        for (int j = 0; j < 4; j++) acc[o][j] = bp;
    }

    const int iy0 = oy0 >> 1, ix0 = ox0 >> 1;
    const int kp = 1 - py, kq = 1 - px;

    for (int ic0 = 0; ic0 < Cin; ic0 += 4) {
        for (int idx = tid; idx < 4 * 324; idx += 128) {
            int icc = idx / 324, p = idx - icc * 324;
            int piy = p / 18, pix = p - piy * 18;
            int iy = iy0 - 1 + piy, ix = ix0 - 1 + pix;
            float v = 0.f;
            if ((unsigned)iy < (unsigned)Hin && (unsigned)ix < (unsigned)Win)
                v = in[(((size_t)b * Cin + ic0 + icc) * Hin + iy) * Win + ix];
            ish[icc][piy * 19 + pix] = v;
        }
        for (int idx = tid; idx < 4 * 48; idx += 128) {
            int icc = idx / 48, rmd = idx - icc * 48;
            wsh[icc][rmd] = wt[(ic0 + icc) * 48 + rmd];
        }
        __syncthreads();

#pragma unroll
        for (int icc = 0; icc < 4; icc++) {
#pragma unroll
            for (int a = 0; a < 2; a++) {
                const int ky  = kp + 2 * a;
                const int liy = ry + 1 + py - a;
                float iv[10];
                const int base = liy * 19 + ch + px;
#pragma unroll
                for (int j = 0; j < 10; j++) iv[j] = ish[icc][base + j];
#pragma unroll
                for (int c = 0; c < 2; c++) {
                    const int kx  = kq + 2 * c;
                    const int t   = ky * 4 + kx;
                    const int off = 1 - c;
                    ull iv2[4];
#pragma unroll
                    for (int jj = 0; jj < 4; jj++)
                        iv2[jj] = pk2(iv[2 * jj + off], iv[2 * jj + 1 + off]);
#pragma unroll
                    for (int o = 0; o < 3; o++) {
                        float w = wsh[icc][o * 16 + t];
                        ull wv = pk2(w, w);
#pragma unroll
                        for (int jj = 0; jj < 4; jj++)
                            acc[o][jj] = ffma2(wv, iv2[jj], acc[o][jj]);
                    }
                }
            }
        }
        __syncthreads();
    }

    const int oy = oy0 + 2 * ry + py;
#pragma unroll
    for (int o = 0; o < 3; o++) {
        float* op = out + (((size_t)b * 3 + o) * Hout + oy) * Wout + ox0 + px + 2 * ch;
        float t0, t1;
#pragma unroll
        for (int jj = 0; jj < 4; jj++) {
            upk2(acc[o][jj], t0, t1);
            op[2 * (2 * jj)]     = t0;
            op[2 * (2 * jj + 1)] = t1;
        }
    }
}

// -------- vector quantize (packed f32x2 dot products) ----------------------
__global__ __launch_bounds__(128, 4)
void vqk(const float* __restrict__ ze, const float* __restrict__ emb,
         float* __restrict__ zq, float* __restrict__ idxf) {
    __shared__ __align__(16) float esh[64 * 64];
    __shared__ float en[64];

    const int row = blockIdx.x * 128 + threadIdx.x;
    ull fv[32];
    const float4* fp = (const float4*)(ze + (size_t)row * 64);
#pragma unroll
    for (int i = 0; i < 16; i++) {
        float4 v = fp[i];
        fv[2 * i]     = pk2(v.x, v.y);
        fv[2 * i + 1] = pk2(v.z, v.w);
    }
    ull nacc = pk2(0.f, 0.f);
#pragma unroll
    for (int i = 0; i < 32; i++) nacc = ffma2(fv[i], fv[i], nacc);
    float nlo, nhi;
    upk2(nacc, nlo, nhi);
    const float fn = nlo + nhi;

    float best = 3.4e38f;
    int bidx = 0;
    for (int cb = 0; cb < 512; cb += 64) {
        __syncthreads();
        const float4* src = (const float4*)(emb + (size_t)cb * 64);
        for (int i = threadIdx.x; i < 1024; i += 128)
            ((float4*)esh)[i] = src[i];
        __syncthreads();
        if (threadIdx.x < 64) {
            const ull* e = (const ull*)(esh + threadIdx.x * 64);
            ull s = pk2(0.f, 0.f);
#pragma unroll
            for (int i = 0; i < 32; i++) s = ffma2(e[i], e[i], s);
            float slo, shi;
            upk2(s, slo, shi);
            en[threadIdx.x] = slo + shi;
        }
        __syncthreads();
        for (int c = 0; c < 64; c++) {
            const ull* ev = (const ull*)(esh + c * 64);
            ull dacc = pk2(0.f, 0.f);
#pragma unroll
            for (int i = 0; i < 32; i++) dacc = ffma2(fv[i], ev[i], dacc);
            float dlo, dhi;
            upk2(dacc, dlo, dhi);
            float sc = fn - 2.f * (dlo + dhi) + en[c];
            if (sc < best) { best = sc; bidx = cb + c; }
        }
    }

    idxf[row] = (float)bidx;
    const float4* ep = (const float4*)(emb + (size_t)bidx * 64);
    float4* qp = (float4*)(zq + (size_t)row * 64);
#pragma unroll
    for (int i = 0; i < 16; i++) qp[i] = ep[i];
}

// ---------------------------------------------------------------------------
extern "C" void kernel_launch(void* const* d_in, const int* in_sizes, int n_in,
                              void* d_out, int out_size) {
    (void)in_sizes; (void)n_in;
    const float* x   = (const float*)d_in[0];
    const float* w1  = (const float*)d_in[1];
    const float* b1  = (const float*)d_in[2];
    const float* w2  = (const float*)d_in[3];
    const float* b2  = (const float*)d_in[4];
    const float* w3  = (const float*)d_in[5];
    const float* b3  = (const float*)d_in[6];
    const float* d1w = (const float*)d_in[7];
    const float* d1b = (const float*)d_in[8];
    const float* d2w = (const float*)d_in[9];
    const float* d2b = (const float*)d_in[10];
    const float* d3w = (const float*)d_in[11];
    const float* d3b = (const float*)d_in[12];
    const float* emb = (const float*)d_in[13];

    float *h1, *h2, *g1, *g2, *ze, *zq, *idxf, *wt1, *wt2, *wt3;
    cudaGetSymbolAddress((void**)&h1, g_h1);
    cudaGetSymbolAddress((void**)&h2, g_h2);
    cudaGetSymbolAddress((void**)&g1, g_g1);
    cudaGetSymbolAddress((void**)&g2, g_g2);
    cudaGetSymbolAddress((void**)&ze, g_ze);
    cudaGetSymbolAddress((void**)&zq, g_zq);
    cudaGetSymbolAddress((void**)&idxf, g_if);
    cudaGetSymbolAddress((void**)&wt1, g_wt1);
    cudaGetSymbolAddress((void**)&wt2, g_wt2);
    cudaGetSymbolAddress((void**)&wt3, g_wt3);

    float* outF = (float*)d_out;
    const int NX = NBATCH * 3 * 256 * 256;
    const int NZ = NBATCH * 64 * 32 * 32;
    const int NI = 16384;
    if (out_size >= NX + 2 * NZ + NI) {
        ze   = outF + NX;
        zq   = outF + NX + NZ;
        idxf = outF + NX + 2 * NZ;
    }

    wtrans<<<(128 * 3 * 16 + 255) / 256, 256>>>(w1, wt1, 128, 3);
    wtrans<<<(256 * 128 * 16 + 255) / 256, 256>>>(w2, wt2, 256, 128);
    wtrans<<<(64 * 256 * 16 + 255) / 256, 256>>>(w3, wt3, 64, 256);

    // encoder
    conv4s2<3, true><<<dim3(64, 2, NBATCH), 256>>>(x, wt1, b1, h1, 128, 256, 256, 128, 128, 8, 1, 0);
    conv4s2<128, true><<<dim3(16, 4, NBATCH), 256>>>(h1, wt2, b2, h2, 256, 128, 128, 64, 64, 4, 1, 0);
    // conv3: 4-way input-channel slab split into scratch (g_g2), then reduce
    conv4s2<64, false><<<dim3(4, 1, NBATCH * 4), 256>>>(h2, wt3, nullptr, g2, 64, 64, 64, 32, 32, 2, 4, NZ);
    addparts<<<NZ / 256, 256>>>(g2, b3, ze);

    // quantize
    vqk<<<128, 128>>>(ze, emb, zq, idxf);

    // decoder
    dconv4s2<true><<<dim3(16, 4, NBATCH), 256>>>(zq, d1w, d1b, g1, 64, 256, 32, 32, 4);
    dconv4s2<true><<<dim3(64, 2, NBATCH), 256>>>(g1, d2w, d2b, g2, 256, 128, 64, 64, 8);
    dconv3out<<<dim3(64, NBATCH), 128>>>(g2, d3w, d3b, outF, 8);
}

// round 3
// speedup vs baseline: 1.6998x; 1.6998x over previous
#include <cuda_runtime.h>

// ---------------------------------------------------------------------------
// VQ-VAE forward, sm_100a.
//   conv2 / dconv2 (85% of FLOPs): mma.sync.m16n8k8.tf32 with 3-term
//   hi/lo split (fp32-class accuracy, ~2e-7 residual).
//   conv1 / conv3 / dconv1 / dconv3 / VQ: scalar-FFMA register-tiled (R1).
// Output layout: [x_recon | z_e | z_q | idx(as float)], fp32.
// ---------------------------------------------------------------------------

#define NBATCH 16

// -------- scratch ------------------------------------------------------------
__device__ float g_h1[NBATCH * 128 * 128 * 128];
__device__ float g_h2[NBATCH * 256 * 64 * 64];
__device__ float g_g1[NBATCH * 256 * 64 * 64];
__device__ float g_g2[NBATCH * 128 * 128 * 128];  // also conv3 partial scratch
__device__ float g_ze[NBATCH * 64 * 32 * 32];
__device__ float g_zq[NBATCH * 64 * 32 * 32];
__device__ float g_if[16384];
__device__ float g_wt1[128 * 3 * 16];
__device__ float g_wt3[64 * 256 * 16];
__device__ float g_wt2t[16 * 128 * 256];   // conv2 weights  [tap][ic][oc]
__device__ float g_wd2t[16 * 256 * 128];   // dconv2 weights [tap][ic][oc]

// -------- mma helpers --------------------------------------------------------
__device__ __forceinline__ void tf32split(float v, unsigned& hi, unsigned& lo) {
    unsigned h;
    asm("cvt.rna.tf32.f32 %0,%1;" : "=r"(h) : "f"(v));
    float l = v - __uint_as_float(h);
    unsigned lw;
    asm("cvt.rna.tf32.f32 %0,%1;" : "=r"(lw) : "f"(l));
    hi = h; lo = lw;
}
__device__ __forceinline__ void mma8(float* c, const unsigned* a,
                                     unsigned b0, unsigned b1) {
    asm("mma.sync.aligned.m16n8k8.row.col.f32.tf32.tf32.f32 "
        "{%0,%1,%2,%3},{%4,%5,%6,%7},{%8,%9},{%0,%1,%2,%3};"
        : "+f"(c[0]), "+f"(c[1]), "+f"(c[2]), "+f"(c[3])
        : "r"(a[0]), "r"(a[1]), "r"(a[2]), "r"(a[3]), "r"(b0), "r"(b1));
}

// -------- weight transposes --------------------------------------------------
__global__ void wtrans(const float* __restrict__ w, float* __restrict__ wo,
                       int Cout, int Cin) {   // OIHW -> [ic][oc][t]
    int idx = blockIdx.x * 256 + threadIdx.x;
    int total = Cout * Cin * 16;
    if (idx < total) {
        int t = idx & 15;
        int rest = idx >> 4;
        int ic = rest % Cin;
        int oc = rest / Cin;
        wo[(ic * Cout + oc) * 16 + t] = w[idx];
    }
}
__global__ void wtrans2t(const float* __restrict__ w, float* __restrict__ wo) {
    // w2 [256oc][128ic][4][4] -> [t][ic(128)][oc(256)]
    int idx = blockIdx.x * 256 + threadIdx.x;   // total 524288
    int t = idx & 15, ic = (idx >> 4) & 127, oc = idx >> 11;
    wo[(t * 128 + ic) * 256 + oc] = w[idx];
}
__global__ void wtransD(const float* __restrict__ w, float* __restrict__ wo) {
    // d2w [256ic][128oc][4][4] -> [t][ic(256)][oc(128)]
    int idx = blockIdx.x * 256 + threadIdx.x;   // total 524288
    int t = idx & 15, oc = (idx >> 4) & 127, ic = idx >> 11;
    wo[(t * 256 + ic) * 128 + oc] = w[idx];
}

// ============================================================================
// conv2 via tf32 MMA:  h1[16,128,128,128] -> h2[16,256,64,64], k4 s2 p1, relu
// CTA: 128 oc x (2 rows x 64 cols).  K-chunk = 8 ic, 16 taps, 3-way split.
// ============================================================================
#define C2_WS   (16 * 8 * 136)       // [tap][icl][oc(128)+pad] stride 136
#define C2_IN   (8 * 6 * 132)        // [icl][6 rows][132 cols]
__global__ __launch_bounds__(256, 2)
void conv2_mma(const float* __restrict__ in, const float* __restrict__ wt,
               const float* __restrict__ bias, float* __restrict__ out) {
    extern __shared__ float sm[];
    float* ws  = sm;            // C2_WS
    float* ins = sm + C2_WS;    // C2_IN

    const int oy0 = blockIdx.x * 2;          // 0..62
    const int ocb = blockIdx.y * 128;        // 0 / 128
    const int b   = blockIdx.z;

    const int tid  = threadIdx.x;
    const int wid  = tid >> 5;
    const int lane = tid & 31;
    const int wm   = wid >> 2;                // 0..1 : M offset 64*wm
    const int wn   = wid & 3;                 // 0..3
    const int oyl  = wn >> 1;                 // row within pair
    const int xb   = (wn & 1) * 32;           // col base
    const int lq   = lane >> 2;               // 0..7
    const int lr   = lane & 3;                // 0..3

    float acc[4][4][4];
#pragma unroll
    for (int mt = 0; mt < 4; mt++)
#pragma unroll
        for (int nt = 0; nt < 4; nt++)
#pragma unroll
            for (int i = 0; i < 4; i++) acc[mt][nt][i] = 0.f;

    const int iy0 = oy0 * 2 - 1;   // staged row 0 -> input row iy0
    const float* inB = in + ((size_t)b * 128) * 128 * 128;

    for (int ch = 0; ch < 16; ch++) {
        // ---- stage input: 8 ic x 6 rows x 132 cols (zero-padded)
        for (int idx = tid; idx < 8 * 6 * 132; idx += 256) {
            int icl = idx / 792;
            int rem = idx - icl * 792;
            int r = rem / 132, c = rem - r * 132;
            int iy = iy0 + r, ix = c - 1;
            float v = 0.f;
            if ((unsigned)iy < 128u && (unsigned)ix < 128u)
                v = inB[((size_t)(ch * 8 + icl) * 128 + iy) * 128 + ix];
            ins[idx] = v;
        }
        // ---- stage weights: 16 taps x 8 ic x 128 oc
        for (int idx = tid; idx < 16384; idx += 256) {
            int oc = idx & 127;
            int icl = (idx >> 7) & 7;
            int t = idx >> 10;
            ws[(t * 8 + icl) * 136 + oc] =
                wt[((size_t)(t * 128 + ch * 8 + icl)) * 256 + ocb + oc];
        }
        __syncthreads();

#pragma unroll 4
        for (int tap = 0; tap < 16; tap++) {
            const int ky = tap >> 2, kx = tap & 3;
            // A fragments (weights) for 4 m-tiles, split hi/lo
            unsigned ahi[4][4], alo[4][4];
#pragma unroll
            for (int mt = 0; mt < 4; mt++) {
                const float* ap = &ws[(tap * 8 + lr) * 136 + wm * 64 + mt * 16 + lq];
                float r0 = ap[0], r1 = ap[8], r2 = ap[4 * 136], r3 = ap[8 + 4 * 136];
                tf32split(r0, ahi[mt][0], alo[mt][0]);
                tf32split(r1, ahi[mt][1], alo[mt][1]);
                tf32split(r2, ahi[mt][2], alo[mt][2]);
                tf32split(r3, ahi[mt][3], alo[mt][3]);
            }
#pragma unroll
            for (int nt = 0; nt < 4; nt++) {
                const int ox = xb + nt * 8 + lq;
                const float* bp = &ins[lr * 792 + (2 * oyl + ky) * 132 + 2 * ox + kx];
                float rb0 = bp[0], rb1 = bp[4 * 792];
                unsigned bh0, bl0, bh1, bl1;
                tf32split(rb0, bh0, bl0);
                tf32split(rb1, bh1, bl1);
#pragma unroll
                for (int mt = 0; mt < 4; mt++) {
                    mma8(acc[mt][nt], ahi[mt], bh0, bh1);
                    mma8(acc[mt][nt], ahi[mt], bl0, bl1);
                    mma8(acc[mt][nt], alo[mt], bh0, bh1);
                }
            }
        }
        __syncthreads();
    }

    // ---- epilogue: bias + relu, direct stores (float2 pairs)
    const int oy = oy0 + oyl;
#pragma unroll
    for (int mt = 0; mt < 4; mt++) {
        const int oc = ocb + wm * 64 + mt * 16 + lq;
        const float b0v = bias[oc], b1v = bias[oc + 8];
#pragma unroll
        for (int nt = 0; nt < 4; nt++) {
            const int ox = xb + nt * 8 + 2 * lr;
            float* o0 = out + (((size_t)b * 256 + oc) * 64 + oy) * 64 + ox;
            float* o1 = o0 + (size_t)8 * 64 * 64;
            float2 v0 = make_float2(fmaxf(acc[mt][nt][0] + b0v, 0.f),
                                    fmaxf(acc[mt][nt][1] + b0v, 0.f));
            float2 v1 = make_float2(fmaxf(acc[mt][nt][2] + b1v, 0.f),
                                    fmaxf(acc[mt][nt][3] + b1v, 0.f));
            *(float2*)o0 = v0;
            *(float2*)o1 = v1;
        }
    }
}

// ============================================================================
// dconv2 via tf32 MMA: g1[16,256,64,64] -> g2[16,128,128,128], relu.
// Per output parity (py,px): 2x2 stride-1 conv, taps (a,c),
//   weight tap t = (1-py+2a)*4 + (1-px+2c),
//   in pixel (y+py-a, x+px-c), out pixel (2y+py, 2x+px).
// CTA: 128 oc x (2 half-rows x 64).  K-chunk = 8 ic.
// ============================================================================
__global__ __launch_bounds__(256, 2)
void dconv2_mma(const float* __restrict__ in, const float* __restrict__ wt,
                const float* __restrict__ bias, float* __restrict__ out) {
    __shared__ float ws[4 * 8 * 136];   // [tl][icl][oc+pad]
    __shared__ float ins[8 * 3 * 68];   // [icl][3 rows][68 cols]

    const int y0 = blockIdx.x * 2;            // half-res row pair
    const int py = blockIdx.y >> 1, px = blockIdx.y & 1;
    const int b  = blockIdx.z;

    const int tid  = threadIdx.x;
    const int wid  = tid >> 5;
    const int lane = tid & 31;
    const int wm   = wid >> 2;
    const int wn   = wid & 3;
    const int yl   = wn >> 1;
    const int xb   = (wn & 1) * 32;
    const int lq   = lane >> 2;
    const int lr   = lane & 3;

    float acc[4][4][4];
#pragma unroll
    for (int mt = 0; mt < 4; mt++)
#pragma unroll
        for (int nt = 0; nt < 4; nt++)
#pragma unroll
            for (int i = 0; i < 4; i++) acc[mt][nt][i] = 0.f;

    const float* inB = in + ((size_t)b * 256) * 64 * 64;

    for (int ch = 0; ch < 32; ch++) {
        // ---- stage input: 8 ic x 3 rows x 66 cols (zero-padded)
        for (int idx = tid; idx < 8 * 3 * 66; idx += 256) {
            int icl = idx / 198;
            int rem = idx - icl * 198;
            int r = rem / 66, s = rem - r * 66;
            int iy = y0 + py - 1 + r;
            int ix = px - 1 + s;
            float v = 0.f;
            if ((unsigned)iy < 64u && (unsigned)ix < 64u)
                v = inB[((size_t)(ch * 8 + icl) * 64 + iy) * 64 + ix];
            ins[(icl * 3 + r) * 68 + s] = v;
        }
        // ---- stage weights: 4 taps x 8 ic x 128 oc
        for (int idx = tid; idx < 4096; idx += 256) {
            int oc = idx & 127;
            int icl = (idx >> 7) & 7;
            int tl = idx >> 10;
            int a = tl >> 1, c = tl & 1;
            int t = (1 - py + 2 * a) * 4 + (1 - px + 2 * c);
            ws[(tl * 8 + icl) * 136 + oc] =
                wt[((size_t)(t * 256 + ch * 8 + icl)) * 128 + oc];
        }
        __syncthreads();

#pragma unroll
        for (int tl = 0; tl < 4; tl++) {
            const int a = tl >> 1, c = tl & 1;
            unsigned ahi[4][4], alo[4][4];
#pragma unroll
            for (int mt = 0; mt < 4; mt++) {
                const float* ap = &ws[(tl * 8 + lr) * 136 + wm * 64 + mt * 16 + lq];
                float r0 = ap[0], r1 = ap[8], r2 = ap[4 * 136], r3 = ap[8 + 4 * 136];
                tf32split(r0, ahi[mt][0], alo[mt][0]);
                tf32split(r1, ahi[mt][1], alo[mt][1]);
                tf32split(r2, ahi[mt][2], alo[mt][2]);
                tf32split(r3, ahi[mt][3], alo[mt][3]);
            }
#pragma unroll
            for (int nt = 0; nt < 4; nt++) {
                const int x = xb + nt * 8 + lq;
                const float* bp = &ins[(lr * 3 + (yl + 1 - a)) * 68 + x + 1 - c];
                float rb0 = bp[0], rb1 = bp[4 * 3 * 68];
                unsigned bh0, bl0, bh1, bl1;
                tf32split(rb0, bh0, bl0);
                tf32split(rb1, bh1, bl1);
#pragma unroll
                for (int mt = 0; mt < 4; mt++) {
                    mma8(acc[mt][nt], ahi[mt], bh0, bh1);
                    mma8(acc[mt][nt], ahi[mt], bl0, bl1);
                    mma8(acc[mt][nt], alo[mt], bh0, bh1);
                }
            }
        }
        __syncthreads();
    }

    // ---- epilogue: out(2y+py, 2x+px), bias + relu
    const int oy = 2 * (y0 + yl) + py;
#pragma unroll
    for (int mt = 0; mt < 4; mt++) {
        const int oc = wm * 64 + mt * 16 + lq;
        const float b0v = bias[oc], b1v = bias[oc + 8];
#pragma unroll
        for (int nt = 0; nt < 4; nt++) {
            const int x = xb + nt * 8 + 2 * lr;
            const int ox = 2 * x + px;
            float* o0 = out + (((size_t)b * 128 + oc) * 128 + oy) * 128 + ox;
            float* o1 = o0 + (size_t)8 * 128 * 128;
            o0[0] = fmaxf(acc[mt][nt][0] + b0v, 0.f);
            o0[2] = fmaxf(acc[mt][nt][1] + b0v, 0.f);
            o1[0] = fmaxf(acc[mt][nt][2] + b1v, 0.f);
            o1[2] = fmaxf(acc[mt][nt][3] + b1v, 0.f);
        }
    }
}

// ============================================================================
// Scalar-FFMA kernels (R1, proven) for conv1 / conv3 / dconv1 / dconv3.
// ============================================================================
template <int CIN, bool RELU>
__global__ __launch_bounds__(256, 2)
void conv4s2(const float* __restrict__ in, const float* __restrict__ wt,
             const float* __restrict__ bias, float* __restrict__ out,
             int Cout, int Hin, int Win, int Hout, int Wout, int tilesX,
             int nSlab, int partStride) {
    __shared__ float ish[34 * 36];
    __shared__ float wsh[64 * 16];

    const int tile = blockIdx.x;
    const int tx0 = (tile % tilesX) * 16;
    const int ty0 = (tile / tilesX) * 16;
    const int ocb = blockIdx.y * 64;
    const int bz  = blockIdx.z;
    const int b    = bz / nSlab;
    const int slab = bz - b * nSlab;

    const int tid = threadIdx.x;
    const int og  = tid >> 5;
    const int sp  = tid & 31;
    const int r   = sp >> 1;
    const int cb  = (sp & 1) * 8;

    float acc[8][8];
#pragma unroll
    for (int o = 0; o < 8; o++) {
        float bv = bias ? bias[ocb + og * 8 + o] : 0.f;
#pragma unroll
        for (int j = 0; j < 8; j++) acc[o][j] = bv;
    }

    const int iy0 = ty0 * 2 - 1, ix0 = tx0 * 2 - 1;
    const float* inB = in + ((size_t)b * (CIN * nSlab) + slab * CIN) * Hin * Win;
    const float* wtS = wt + (size_t)slab * CIN * Cout * 16;

    for (int ic = 0; ic < CIN; ic++) {
        const float* inC = inB + (size_t)ic * Hin * Win;
        for (int idx = tid; idx < 34 * 34; idx += 256) {
            int py = idx / 34, px = idx - py * 34;
            int iy = iy0 + py, ix = ix0 + px;
            float v = 0.f;
            if ((unsigned)iy < (unsigned)Hin && (unsigned)ix < (unsigned)Win)
                v = inC[iy * Win + ix];
            ish[py * 36 + px] = v;
        }
        const float* wC = wtS + (ic * Cout + ocb) * 16;
        for (int idx = tid; idx < 1024; idx += 256) wsh[idx] = wC[idx];
        __syncthreads();

#pragma unroll
        for (int ky = 0; ky < 4; ky++) {
            const float* rp = &ish[(2 * r + ky) * 36 + 2 * cb];
            float4 v0 = *(const float4*)(rp);
            float4 v1 = *(const float4*)(rp + 4);
            float4 v2 = *(const float4*)(rp + 8);
            float4 v3 = *(const float4*)(rp + 12);
            float4 v4 = *(const float4*)(rp + 16);
            float riv[20] = {v0.x, v0.y, v0.z, v0.w, v1.x, v1.y, v1.z, v1.w,
                             v2.x, v2.y, v2.z, v2.w, v3.x, v3.y, v3.z, v3.w,
                             v4.x, v4.y, v4.z, v4.w};
#pragma unroll
            for (int kx = 0; kx < 4; kx++) {
                const int t = ky * 4 + kx;
                float wv[8];
#pragma unroll
                for (int o = 0; o < 8; o++) wv[o] = wsh[(og * 8 + o) * 16 + t];
#pragma unroll
                for (int o = 0; o < 8; o++)
#pragma unroll
                    for (int j = 0; j < 8; j++)
                        acc[o][j] = fmaf(wv[o], riv[kx + 2 * j], acc[o][j]);
            }
        }
        __syncthreads();
    }

    const int oy = ty0 + r;
    const int oxb = tx0 + cb;
    float* outS = out + (size_t)slab * partStride;
#pragma unroll
    for (int o = 0; o < 8; o++) {
        float* op = outS + (((size_t)b * Cout + ocb + og * 8 + o) * Hout + oy) * Wout + oxb;
        float tmp[8];
#pragma unroll
        for (int j = 0; j < 8; j++)
            tmp[j] = RELU ? fmaxf(acc[o][j], 0.f) : acc[o][j];
        *(float4*)op       = make_float4(tmp[0], tmp[1], tmp[2], tmp[3]);
        *(float4*)(op + 4) = make_float4(tmp[4], tmp[5], tmp[6], tmp[7]);
    }
}

__global__ void addparts(const float* __restrict__ p, const float* __restrict__ bias,
                         float* __restrict__ ze) {
    const int S = NBATCH * 64 * 32 * 32;
    int i = blockIdx.x * 256 + threadIdx.x;
    float v = p[i] + p[i + S] + p[i + 2 * S] + p[i + 3 * S];
    ze[i] = v + bias[(i >> 10) & 63];
}

template <bool RELU>
__global__ __launch_bounds__(256, 2)
void dconv4s2(const float* __restrict__ in, const float* __restrict__ wt,
              const float* __restrict__ bias, float* __restrict__ out,
              int Cin, int Cout, int Hin, int Win, int tilesX) {
    const int Hout = Hin * 2, Wout = Win * 2;
    __shared__ float wsh[4][64 * 16];
    __shared__ float ish[4][10 * 16];

    const int tile = blockIdx.x;
    const int ox0 = (tile % tilesX) * 16;
    const int oy0 = (tile / tilesX) * 16;
    const int ocb = blockIdx.y * 64;
    const int b   = blockIdx.z;

    const int tid = threadIdx.x;
    const int og  = tid >> 5;
    const int sp  = tid & 31;
    const int q   = sp >> 3;
    const int py  = q >> 1, px = q & 1;
    const int ry  = sp & 7;

    float acc[8][8];
#pragma unroll
    for (int o = 0; o < 8; o++) {
        float bv = bias[ocb + og * 8 + o];
#pragma unroll
        for (int j = 0; j < 8; j++) acc[o][j] = bv;
    }

    const int iy0 = oy0 >> 1, ix0 = ox0 >> 1;
    const int kp = 1 - py;
    const int kq = 1 - px;

    for (int ic0 = 0; ic0 < Cin; ic0 += 4) {
        for (int idx = tid; idx < 4 * 100; idx += 256) {
            int icc = idx / 100, p = idx - icc * 100;
            int piy = p / 10, pix = p - piy * 10;
            int iy = iy0 - 1 + piy, ix = ix0 - 1 + pix;
            float v = 0.f;
            if ((unsigned)iy < (unsigned)Hin && (unsigned)ix < (unsigned)Win)
                v = in[(((size_t)b * Cin + ic0 + icc) * Hin + iy) * Win + ix];
            ish[icc][piy * 16 + pix] = v;
        }
        for (int idx = tid; idx < 4 * 1024; idx += 256) {
            int icc = idx >> 10, rmd = idx & 1023;
            wsh[icc][rmd] = wt[((ic0 + icc) * Cout + ocb) * 16 + rmd];
        }
        __syncthreads();

#pragma unroll
        for (int icc = 0; icc < 4; icc++) {
#pragma unroll
            for (int a = 0; a < 2; a++) {
                const int ky  = kp + 2 * a;
                const int liy = ry + 1 + py - a;
                const float* rp = &ish[icc][liy * 16];
                float4 u0 = *(const float4*)(rp);
                float4 u1 = *(const float4*)(rp + 4);
                float2 u2 = *(const float2*)(rp + 8);
                float riv[10] = {u0.x, u0.y, u0.z, u0.w,
                                 u1.x, u1.y, u1.z, u1.w, u2.x, u2.y};
#pragma unroll
                for (int c = 0; c < 2; c++) {
                    const int kx = kq + 2 * c;
                    const int cc = px - c + 1;
                    const int t  = ky * 4 + kx;
                    float wv[8];
#pragma unroll
                    for (int o = 0; o < 8; o++)
                        wv[o] = wsh[icc][(og * 8 + o) * 16 + t];
#pragma unroll
                    for (int o = 0; o < 8; o++)
#pragma unroll
                        for (int j = 0; j < 8; j++)
                            acc[o][j] = fmaf(wv[o], riv[cc + j], acc[o][j]);
                }
            }
        }
        __syncthreads();
    }

    const int oy = oy0 + 2 * ry + py;
#pragma unroll
    for (int o = 0; o < 8; o++) {
        float* op = out + (((size_t)b * Cout + ocb + og * 8 + o) * Hout + oy) * Wout + ox0 + px;
#pragma unroll
        for (int j = 0; j < 8; j++) {
            float v = acc[o][j];
            if (RELU) v = fmaxf(v, 0.f);
            op[2 * j] = v;
        }
    }
}

__global__ __launch_bounds__(128, 4)
void dconv3out(const float* __restrict__ in, const float* __restrict__ wt,
               const float* __restrict__ bias, float* __restrict__ out,
               int tilesX) {
    const int Cin = 128, Hin = 128, Win = 128, Hout = 256, Wout = 256;
    __shared__ float ish[4][18 * 19];
    __shared__ float wsh[4][3 * 16];

    const int tile = blockIdx.x;
    const int ox0 = (tile % tilesX) * 32;
    const int oy0 = (tile / tilesX) * 32;
    const int b   = blockIdx.y;

    const int tid = threadIdx.x;
    const int q   = tid >> 5;
    const int py  = q >> 1, px = q & 1;
    const int sp  = tid & 31;
    const int ry  = sp >> 1;
    const int ch  = (sp & 1) * 8;

    float acc[3][8];
#pragma unroll
    for (int o = 0; o < 3; o++) {
        float bv = bias[o];
#pragma unroll
        for (int j = 0; j < 8; j++) acc[o][j] = bv;
    }

    const int iy0 = oy0 >> 1, ix0 = ox0 >> 1;
    const int kp = 1 - py, kq = 1 - px;

    for (int ic0 = 0; ic0 < Cin; ic0 += 4) {
        for (int idx = tid; idx < 4 * 324; idx += 128) {
            int icc = idx / 324, p = idx - icc * 324;
            int piy = p / 18, pix = p - piy * 18;
            int iy = iy0 - 1 + piy, ix = ix0 - 1 + pix;
            float v = 0.f;
            if ((unsigned)iy < (unsigned)Hin && (unsigned)ix < (unsigned)Win)
                v = in[(((size_t)b * Cin + ic0 + icc) * Hin + iy) * Win + ix];
            ish[icc][piy * 19 + pix] = v;
        }
        for (int idx = tid; idx < 4 * 48; idx += 128) {
            int icc = idx / 48, rmd = idx - icc * 48;
            wsh[icc][rmd] = wt[(ic0 + icc) * 48 + rmd];
        }
        __syncthreads();

#pragma unroll
        for (int icc = 0; icc < 4; icc++) {
#pragma unroll
            for (int a = 0; a < 2; a++) {
                const int ky  = kp + 2 * a;
                const int liy = ry + 1 + py - a;
                float iv[10];
                const int base = liy * 19 + ch + px;
#pragma unroll
                for (int j = 0; j < 10; j++) iv[j] = ish[icc][base + j];
#pragma unroll
                for (int c = 0; c < 2; c++) {
                    const int kx  = kq + 2 * c;
                    const int t   = ky * 4 + kx;
                    const int off = 1 - c;
                    float wv[3];
#pragma unroll
                    for (int o = 0; o < 3; o++) wv[o] = wsh[icc][o * 16 + t];
#pragma unroll
                    for (int o = 0; o < 3; o++)
#pragma unroll
                        for (int j = 0; j < 8; j++)
                            acc[o][j] = fmaf(wv[o], iv[j + off], acc[o][j]);
                }
            }
        }
        __syncthreads();
    }

    const int oy = oy0 + 2 * ry + py;
#pragma unroll
    for (int o = 0; o < 3; o++) {
        float* op = out + (((size_t)b * 3 + o) * Hout + oy) * Wout + ox0 + px + 2 * ch;
#pragma unroll
        for (int j = 0; j < 8; j++) op[2 * j] = acc[o][j];
    }
}

// -------- vector quantize ----------------------------------------------------
__global__ __launch_bounds__(128, 8)
void vqk(const float* __restrict__ ze, const float* __restrict__ emb,
         float* __restrict__ zq, float* __restrict__ idxf) {
    __shared__ __align__(16) float esh[64 * 64];
    __shared__ float en[64];

    const int row = blockIdx.x * 128 + threadIdx.x;
    float f[64];
    const float4* fp = (const float4*)(ze + (size_t)row * 64);
#pragma unroll
    for (int i = 0; i < 16; i++) {
        float4 v = fp[i];
        f[4 * i] = v.x; f[4 * i + 1] = v.y; f[4 * i + 2] = v.z; f[4 * i + 3] = v.w;
    }
    float fn = 0.f;
#pragma unroll
    for (int d = 0; d < 64; d++) fn = fmaf(f[d], f[d], fn);

    float best = 3.4e38f;
    int bidx = 0;
    for (int cb = 0; cb < 512; cb += 64) {
        __syncthreads();
        const float4* src = (const float4*)(emb + (size_t)cb * 64);
        for (int i = threadIdx.x; i < 1024; i += 128)
            ((float4*)esh)[i] = src[i];
        __syncthreads();
        if (threadIdx.x < 64) {
            float s = 0.f;
            const float* e = esh + threadIdx.x * 64;
#pragma unroll
            for (int d = 0; d < 64; d++) s = fmaf(e[d], e[d], s);
            en[threadIdx.x] = s;
        }
        __syncthreads();
        for (int c = 0; c < 64; c++) {
            const float4* ev = (const float4*)(esh + c * 64);
            float dot = 0.f;
#pragma unroll
            for (int i = 0; i < 16; i++) {
                float4 e = ev[i];
                dot = fmaf(f[4 * i], e.x, dot);
                dot = fmaf(f[4 * i + 1], e.y, dot);
                dot = fmaf(f[4 * i + 2], e.z, dot);
                dot = fmaf(f[4 * i + 3], e.w, dot);
            }
            float sc = fn - 2.f * dot + en[c];
            if (sc < best) { best = sc; bidx = cb + c; }
        }
    }

    idxf[row] = (float)bidx;
    const float4* ep = (const float4*)(emb + (size_t)bidx * 64);
    float4* qp = (float4*)(zq + (size_t)row * 64);
#pragma unroll
    for (int i = 0; i < 16; i++) qp[i] = ep[i];
}

// ---------------------------------------------------------------------------
extern "C" void kernel_launch(void* const* d_in, const int* in_sizes, int n_in,
                              void* d_out, int out_size) {
    (void)in_sizes; (void)n_in;
    const float* x   = (const float*)d_in[0];
    const float* w1  = (const float*)d_in[1];
    const float* b1  = (const float*)d_in[2];
    const float* w2  = (const float*)d_in[3];
    const float* b2  = (const float*)d_in[4];
    const float* w3  = (const float*)d_in[5];
    const float* b3  = (const float*)d_in[6];
    const float* d1w = (const float*)d_in[7];
    const float* d1b = (const float*)d_in[8];
    const float* d2w = (const float*)d_in[9];
    const float* d2b = (const float*)d_in[10];
    const float* d3w = (const float*)d_in[11];
    const float* d3b = (const float*)d_in[12];
    const float* emb = (const float*)d_in[13];

    float *h1, *h2, *g1, *g2, *ze, *zq, *idxf, *wt1, *wt3, *wt2t, *wd2t;
    cudaGetSymbolAddress((void**)&h1, g_h1);
    cudaGetSymbolAddress((void**)&h2, g_h2);
    cudaGetSymbolAddress((void**)&g1, g_g1);
    cudaGetSymbolAddress((void**)&g2, g_g2);
    cudaGetSymbolAddress((void**)&ze, g_ze);
    cudaGetSymbolAddress((void**)&zq, g_zq);
    cudaGetSymbolAddress((void**)&idxf, g_if);
    cudaGetSymbolAddress((void**)&wt1, g_wt1);
    cudaGetSymbolAddress((void**)&wt3, g_wt3);
    cudaGetSymbolAddress((void**)&wt2t, g_wt2t);
    cudaGetSymbolAddress((void**)&wd2t, g_wd2t);

    float* outF = (float*)d_out;
    const int NX = NBATCH * 3 * 256 * 256;
    const int NZ = NBATCH * 64 * 32 * 32;
    const int NI = 16384;
    if (out_size >= NX + 2 * NZ + NI) {
        ze   = outF + NX;
        zq   = outF + NX + NZ;
        idxf = outF + NX + 2 * NZ;
    }

    static bool attr_done = false;
    if (!attr_done) {
        cudaFuncSetAttribute(conv2_mma, cudaFuncAttributeMaxDynamicSharedMemorySize,
                             (C2_WS + C2_IN) * 4);
        attr_done = true;
    }

    // weight reshapes (tiny)
    wtrans<<<(128 * 3 * 16 + 255) / 256, 256>>>(w1, wt1, 128, 3);
    wtrans<<<(64 * 256 * 16 + 255) / 256, 256>>>(w3, wt3, 64, 256);
    wtrans2t<<<2048, 256>>>(w2, wt2t);
    wtransD<<<2048, 256>>>(d2w, wd2t);

    // encoder
    conv4s2<3, true><<<dim3(64, 2, NBATCH), 256>>>(x, wt1, b1, h1, 128, 256, 256, 128, 128, 8, 1, 0);
    conv2_mma<<<dim3(32, 2, NBATCH), 256, (C2_WS + C2_IN) * 4>>>(h1, wt2t, b2, h2);
    conv4s2<64, false><<<dim3(4, 1, NBATCH * 4), 256>>>(h2, wt3, nullptr, g2, 64, 64, 64, 32, 32, 2, 4, NZ);
    addparts<<<NZ / 256, 256>>>(g2, b3, ze);

    // quantize
    vqk<<<128, 128>>>(ze, emb, zq, idxf);

    // decoder
    dconv4s2<true><<<dim3(16, 4, NBATCH), 256>>>(zq, d1w, d1b, g1, 64, 256, 32, 32, 4);
    dconv2_mma<<<dim3(32, 4, NBATCH), 256>>>(g1, wd2t, d2b, g2);
    dconv3out<<<dim3(64, NBATCH), 128>>>(g2, d3w, d3b, outF, 8);
}

// round 4
// speedup vs baseline: 1.7400x; 1.0236x over previous
#include <cuda_runtime.h>

// ---------------------------------------------------------------------------
// VQ-VAE forward, sm_100a.
//   conv2 / conv3 / dconv1 / dconv2 : mma.sync.m16n8k8.tf32, 3-term hi/lo
//     split; weights PRE-SPLIT into interleaved (hi,lo) tf32 pairs in gmem.
//   conv1 / dconv3 / VQ: scalar-FFMA register-tiled.
// Output layout: [x_recon | z_e | z_q | idx(as float)], fp32.
// ---------------------------------------------------------------------------

#define NBATCH 16

// -------- scratch ------------------------------------------------------------
__device__ float g_h1[NBATCH * 128 * 128 * 128];
__device__ float g_h2[NBATCH * 256 * 64 * 64];
__device__ float g_g1[NBATCH * 256 * 64 * 64];
__device__ float g_g2[NBATCH * 128 * 128 * 128];  // also conv3 partial scratch
__device__ float g_ze[NBATCH * 64 * 32 * 32];
__device__ float g_zq[NBATCH * 64 * 32 * 32];
__device__ float g_if[16384];
__device__ float g_wt1[128 * 3 * 16];
__device__ float2 g_w2s[16 * 128 * 256];   // conv2  [t][ic][oc] (hi,lo)
__device__ float2 g_d2s[16 * 256 * 128];   // dconv2 [t][ic][oc]
__device__ float2 g_d1s[16 * 64 * 256];    // dconv1 [t][ic][oc]
__device__ float2 g_w3s[16 * 256 * 64];    // conv3  [t][ic][oc]

// -------- mma helpers --------------------------------------------------------
__device__ __forceinline__ void tf32split(float v, unsigned& hi, unsigned& lo) {
    unsigned h;
    asm("cvt.rna.tf32.f32 %0,%1;" : "=r"(h) : "f"(v));
    float l = v - __uint_as_float(h);
    unsigned lw;
    asm("cvt.rna.tf32.f32 %0,%1;" : "=r"(lw) : "f"(l));
    hi = h; lo = lw;
}
__device__ __forceinline__ float2 splitpack(float v) {
    unsigned h, l;
    tf32split(v, h, l);
    return make_float2(__uint_as_float(h), __uint_as_float(l));
}
__device__ __forceinline__ void mma8(float* c, const unsigned* a,
                                     unsigned b0, unsigned b1) {
    asm("mma.sync.aligned.m16n8k8.row.col.f32.tf32.tf32.f32 "
        "{%0,%1,%2,%3},{%4,%5,%6,%7},{%8,%9},{%0,%1,%2,%3};"
        : "+f"(c[0]), "+f"(c[1]), "+f"(c[2]), "+f"(c[3])
        : "r"(a[0]), "r"(a[1]), "r"(a[2]), "r"(a[3]), "r"(b0), "r"(b1));
}

// -------- weight transforms --------------------------------------------------
__global__ void wtrans(const float* __restrict__ w, float* __restrict__ wo,
                       int Cout, int Cin) {   // OIHW -> [ic][oc][t]
    int idx = blockIdx.x * 256 + threadIdx.x;
    int total = Cout * Cin * 16;
    if (idx < total) {
        int t = idx & 15;
        int rest = idx >> 4;
        int ic = rest % Cin;
        int oc = rest / Cin;
        wo[(ic * Cout + oc) * 16 + t] = w[idx];
    }
}
__global__ void wsplit2t(const float* __restrict__ w, float2* __restrict__ wo) {
    // w2 [256oc][128ic][16] -> [t][ic128][oc256] hilo
    int idx = blockIdx.x * 256 + threadIdx.x;   // 524288
    int t = idx & 15, ic = (idx >> 4) & 127, oc = idx >> 11;
    wo[(t * 128 + ic) * 256 + oc] = splitpack(w[idx]);
}
__global__ void wsplitD2(const float* __restrict__ w, float2* __restrict__ wo) {
    // d2w [256ic][128oc][16] -> [t][ic256][oc128] hilo
    int idx = blockIdx.x * 256 + threadIdx.x;   // 524288
    int t = idx & 15, oc = (idx >> 4) & 127, ic = idx >> 11;
    wo[(t * 256 + ic) * 128 + oc] = splitpack(w[idx]);
}
__global__ void wsplitD1(const float* __restrict__ w, float2* __restrict__ wo) {
    // d1w [64ic][256oc][16] -> [t][ic64][oc256] hilo
    int idx = blockIdx.x * 256 + threadIdx.x;   // 262144
    int t = idx & 15, oc = (idx >> 4) & 255, ic = idx >> 12;
    wo[(t * 64 + ic) * 256 + oc] = splitpack(w[idx]);
}
__global__ void wsplit3(const float* __restrict__ w, float2* __restrict__ wo) {
    // w3 [64oc][256ic][16] -> [t][ic256][oc64] hilo
    int idx = blockIdx.x * 256 + threadIdx.x;   // 262144
    int t = idx & 15, ic = (idx >> 4) & 255, oc = idx >> 12;
    wo[(t * 256 + ic) * 64 + oc] = splitpack(w[idx]);
}

// ============================================================================
// conv2 MMA: h1[16,128,128,128] -> h2[16,256,64,64], k4 s2 p1, relu.
// CTA: 128 oc x (2 rows x 64 cols).  Weights pre-split, staged 4 taps/chunk.
// ============================================================================
#define C2_WS2 (4 * 8 * 132)     // float2
#define C2_INS (8 * 6 * 132)     // float
__global__ __launch_bounds__(256, 2)
void conv2_mma(const float* __restrict__ in, const float2* __restrict__ wt,
               const float* __restrict__ bias, float* __restrict__ out) {
    extern __shared__ float sm[];
    float2* ws = (float2*)sm;
    float* ins = sm + 2 * C2_WS2;

    const int oy0 = blockIdx.x * 2;
    const int ocb = blockIdx.y * 128;
    const int b   = blockIdx.z;

    const int tid  = threadIdx.x;
    const int wid  = tid >> 5;
    const int lane = tid & 31;
    const int wm   = wid >> 2;
    const int wn   = wid & 3;
    const int oyl  = wn >> 1;
    const int xb   = (wn & 1) * 32;
    const int lq   = lane >> 2;
    const int lr   = lane & 3;

    float acc[4][4][4];
#pragma unroll
    for (int mt = 0; mt < 4; mt++)
#pragma unroll
        for (int nt = 0; nt < 4; nt++)
#pragma unroll
            for (int i = 0; i < 4; i++) acc[mt][nt][i] = 0.f;

    const int iy0 = oy0 * 2 - 1;
    const float* inB = in + ((size_t)b * 128) * 128 * 128;

    for (int ch = 0; ch < 16; ch++) {
        // stage input: 8 ic x 6 rows x 132 cols (zero-padded)
        for (int idx = tid; idx < 8 * 6 * 132; idx += 256) {
            int icl = idx / 792;
            int rem = idx - icl * 792;
            int r = rem / 132, c = rem - r * 132;
            int iy = iy0 + r, ix = c - 1;
            float v = 0.f;
            if ((unsigned)iy < 128u && (unsigned)ix < 128u)
                v = inB[((size_t)(ch * 8 + icl) * 128 + iy) * 128 + ix];
            ins[idx] = v;
        }
        for (int tg = 0; tg < 4; tg++) {
            // stage weights: 4 taps x 8 ic x 128 oc (hilo)
            for (int idx = tid; idx < 4096; idx += 256) {
                int oc = idx & 127;
                int icl = (idx >> 7) & 7;
                int tl = idx >> 10;
                ws[(tl * 8 + icl) * 132 + oc] =
                    wt[((size_t)((tg * 4 + tl) * 128 + ch * 8 + icl)) * 256 + ocb + oc];
            }
            __syncthreads();

#pragma unroll
            for (int tapl = 0; tapl < 4; tapl++) {
                const int ky = tg, kx = tapl;
                unsigned ahi[4][4], alo[4][4];
#pragma unroll
                for (int mt = 0; mt < 4; mt++) {
                    const float2* ap = &ws[(tapl * 8 + lr) * 132 + wm * 64 + mt * 16 + lq];
                    float2 p0 = ap[0], p1 = ap[8], p2 = ap[4 * 132], p3 = ap[4 * 132 + 8];
                    ahi[mt][0] = __float_as_uint(p0.x); alo[mt][0] = __float_as_uint(p0.y);
                    ahi[mt][1] = __float_as_uint(p1.x); alo[mt][1] = __float_as_uint(p1.y);
                    ahi[mt][2] = __float_as_uint(p2.x); alo[mt][2] = __float_as_uint(p2.y);
                    ahi[mt][3] = __float_as_uint(p3.x); alo[mt][3] = __float_as_uint(p3.y);
                }
#pragma unroll
                for (int nt = 0; nt < 4; nt++) {
                    const int ox = xb + nt * 8 + lq;
                    const float* bp = &ins[lr * 792 + (2 * oyl + ky) * 132 + 2 * ox + kx];
                    float rb0 = bp[0], rb1 = bp[4 * 792];
                    unsigned bh0, bl0, bh1, bl1;
                    tf32split(rb0, bh0, bl0);
                    tf32split(rb1, bh1, bl1);
#pragma unroll
                    for (int mt = 0; mt < 4; mt++) {
                        mma8(acc[mt][nt], ahi[mt], bh0, bh1);
                        mma8(acc[mt][nt], ahi[mt], bl0, bl1);
                        mma8(acc[mt][nt], alo[mt], bh0, bh1);
                    }
                }
            }
            __syncthreads();
        }
    }

    const int oy = oy0 + oyl;
#pragma unroll
    for (int mt = 0; mt < 4; mt++) {
        const int oc = ocb + wm * 64 + mt * 16 + lq;
        const float b0v = bias[oc], b1v = bias[oc + 8];
#pragma unroll
        for (int nt = 0; nt < 4; nt++) {
            const int ox = xb + nt * 8 + 2 * lr;
            float* o0 = out + (((size_t)b * 256 + oc) * 64 + oy) * 64 + ox;
            float* o1 = o0 + (size_t)8 * 64 * 64;
            *(float2*)o0 = make_float2(fmaxf(acc[mt][nt][0] + b0v, 0.f),
                                       fmaxf(acc[mt][nt][1] + b0v, 0.f));
            *(float2*)o1 = make_float2(fmaxf(acc[mt][nt][2] + b1v, 0.f),
                                       fmaxf(acc[mt][nt][3] + b1v, 0.f));
        }
    }
}

// ============================================================================
// conv3 MMA: h2[16,256,64,64] -> partials[slab][16,64,32,32], k4 s2 p1.
// M=64 oc, N=8 rows x 32 cols, K-slab 64 ic per CTA (4 slabs).
// ============================================================================
#define C3_WS2 (4 * 8 * 68)      // float2
#define C3_INS (8 * 18 * 68)     // float
__global__ __launch_bounds__(256, 2)
void conv3_mma(const float* __restrict__ in, const float2* __restrict__ wt,
               float* __restrict__ outp) {
    extern __shared__ float sm[];
    float2* ws = (float2*)sm;
    float* ins = sm + 2 * C3_WS2;

    const int r0   = blockIdx.x * 8;
    const int b    = blockIdx.z >> 2;
    const int slab = blockIdx.z & 3;

    const int tid  = threadIdx.x;
    const int w    = tid >> 5;              // warp -> out row r0+w
    const int lane = tid & 31;
    const int lq   = lane >> 2;
    const int lr   = lane & 3;

    float acc[4][4][4];
#pragma unroll
    for (int mt = 0; mt < 4; mt++)
#pragma unroll
        for (int nt = 0; nt < 4; nt++)
#pragma unroll
            for (int i = 0; i < 4; i++) acc[mt][nt][i] = 0.f;

    const int iy0 = r0 * 2 - 1;
    const float* inB = in + ((size_t)b * 256 + slab * 64) * 64 * 64;

    for (int ch = 0; ch < 8; ch++) {
        for (int idx = tid; idx < 8 * 18 * 66; idx += 256) {
            int icl = idx / 1188;
            int rem = idx - icl * 1188;
            int r = rem / 66, c = rem - r * 66;
            int iy = iy0 + r, ix = c - 1;
            float v = 0.f;
            if ((unsigned)iy < 64u && (unsigned)ix < 64u)
                v = inB[((size_t)(ch * 8 + icl) * 64 + iy) * 64 + ix];
            ins[icl * 1224 + r * 68 + c] = v;
        }
        for (int tg = 0; tg < 4; tg++) {
            for (int idx = tid; idx < 2048; idx += 256) {
                int oc = idx & 63;
                int icl = (idx >> 6) & 7;
                int tl = idx >> 9;
                ws[(tl * 8 + icl) * 68 + oc] =
                    wt[((size_t)((tg * 4 + tl) * 256 + slab * 64 + ch * 8 + icl)) * 64 + oc];
            }
            __syncthreads();

#pragma unroll
            for (int tapl = 0; tapl < 4; tapl++) {
                const int ky = tg, kx = tapl;
                unsigned ahi[4][4], alo[4][4];
#pragma unroll
                for (int mt = 0; mt < 4; mt++) {
                    const float2* ap = &ws[(tapl * 8 + lr) * 68 + mt * 16 + lq];
                    float2 p0 = ap[0], p1 = ap[8], p2 = ap[4 * 68], p3 = ap[4 * 68 + 8];
                    ahi[mt][0] = __float_as_uint(p0.x); alo[mt][0] = __float_as_uint(p0.y);
                    ahi[mt][1] = __float_as_uint(p1.x); alo[mt][1] = __float_as_uint(p1.y);
                    ahi[mt][2] = __float_as_uint(p2.x); alo[mt][2] = __float_as_uint(p2.y);
                    ahi[mt][3] = __float_as_uint(p3.x); alo[mt][3] = __float_as_uint(p3.y);
                }
#pragma unroll
                for (int nt = 0; nt < 4; nt++) {
                    const int col = nt * 8 + lq;
                    const float* bp = &ins[lr * 1224 + (2 * w + ky) * 68 + 2 * col + kx];
                    float rb0 = bp[0], rb1 = bp[4 * 1224];
                    unsigned bh0, bl0, bh1, bl1;
                    tf32split(rb0, bh0, bl0);
                    tf32split(rb1, bh1, bl1);
#pragma unroll
                    for (int mt = 0; mt < 4; mt++) {
                        mma8(acc[mt][nt], ahi[mt], bh0, bh1);
                        mma8(acc[mt][nt], ahi[mt], bl0, bl1);
                        mma8(acc[mt][nt], alo[mt], bh0, bh1);
                    }
                }
            }
            __syncthreads();
        }
    }

    const int NZ = NBATCH * 64 * 32 * 32;
    float* part = outp + (size_t)slab * NZ;
    const int row = r0 + w;
#pragma unroll
    for (int mt = 0; mt < 4; mt++) {
        const int oc = mt * 16 + lq;
#pragma unroll
        for (int nt = 0; nt < 4; nt++) {
            float* o0 = part + (((size_t)b * 64 + oc) * 32 + row) * 32 + nt * 8 + 2 * lr;
            float* o1 = o0 + (size_t)8 * 32 * 32;
            *(float2*)o0 = make_float2(acc[mt][nt][0], acc[mt][nt][1]);
            *(float2*)o1 = make_float2(acc[mt][nt][2], acc[mt][nt][3]);
        }
    }
}

__global__ void addparts(const float* __restrict__ p, const float* __restrict__ bias,
                         float* __restrict__ ze) {
    const int S = NBATCH * 64 * 32 * 32;
    int i = blockIdx.x * 256 + threadIdx.x;
    float v = p[i] + p[i + S] + p[i + 2 * S] + p[i + 3 * S];
    ze[i] = v + bias[(i >> 10) & 63];
}

// ============================================================================
// dconv MMA (shared template for dconv1 & dconv2): parity-decomposed 2x2 conv.
//   CIN ic, 128-oc block, CTA = 2 half-rows x WHALF cols of half-res grid.
// ============================================================================
template <int CIN, int HIN>   // dconv1: CIN=64,HIN=32  dconv2: CIN=256,HIN=64
__global__ __launch_bounds__(256, 2)
void dconv_mma(const float* __restrict__ in, const float2* __restrict__ wt,
               const float* __restrict__ bias, float* __restrict__ out,
               int Cout, int nOcb) {
    const int WROW = HIN + 2;               // staged cols (HIN+2), stride +2 pad
    __shared__ float2 ws[4 * 8 * 132];
    __shared__ float ins[8 * 3 * (HIN + 4)];

    const int y0 = blockIdx.x * 2;
    const int py = blockIdx.y >> 1, px = blockIdx.y & 1;
    const int b   = blockIdx.z / nOcb;
    const int ocb = (blockIdx.z % nOcb) * 128;

    const int tid  = threadIdx.x;
    const int wid  = tid >> 5;
    const int lane = tid & 31;
    const int wm   = wid >> 2;
    const int wn   = wid & 3;
    const int yl   = wn >> 1;
    const int xb   = (wn & 1) * (HIN / 2);
    const int lq   = lane >> 2;
    const int lr   = lane & 3;
    const int NT   = HIN / 16;              // n-tiles per warp (2 or 4)

    const int ISTR = HIN + 4;

    float acc[4][4][4];
#pragma unroll
    for (int mt = 0; mt < 4; mt++)
#pragma unroll
        for (int nt = 0; nt < 4; nt++)
#pragma unroll
            for (int i = 0; i < 4; i++) acc[mt][nt][i] = 0.f;

    const float* inB = in + ((size_t)b * CIN) * HIN * HIN;

    for (int ch = 0; ch < CIN / 8; ch++) {
        for (int idx = tid; idx < 8 * 3 * WROW; idx += 256) {
            int icl = idx / (3 * WROW);
            int rem = idx - icl * 3 * WROW;
            int r = rem / WROW, s = rem - r * WROW;
            int iy = y0 + py - 1 + r;
            int ix = px - 1 + s;
            float v = 0.f;
            if ((unsigned)iy < (unsigned)HIN && (unsigned)ix < (unsigned)HIN)
                v = inB[((size_t)(ch * 8 + icl) * HIN + iy) * HIN + ix];
            ins[(icl * 3 + r) * ISTR + s] = v;
        }
        for (int idx = tid; idx < 4096; idx += 256) {
            int oc = idx & 127;
            int icl = (idx >> 7) & 7;
            int tl = idx >> 10;
            int a = tl >> 1, c = tl & 1;
            int t = (1 - py + 2 * a) * 4 + (1 - px + 2 * c);
            ws[(tl * 8 + icl) * 132 + oc] =
                wt[((size_t)(t * CIN + ch * 8 + icl)) * Cout + ocb + oc];
        }
        __syncthreads();

#pragma unroll
        for (int tl = 0; tl < 4; tl++) {
            const int a = tl >> 1, c = tl & 1;
            unsigned ahi[4][4], alo[4][4];
#pragma unroll
            for (int mt = 0; mt < 4; mt++) {
                const float2* ap = &ws[(tl * 8 + lr) * 132 + wm * 64 + mt * 16 + lq];
                float2 p0 = ap[0], p1 = ap[8], p2 = ap[4 * 132], p3 = ap[4 * 132 + 8];
                ahi[mt][0] = __float_as_uint(p0.x); alo[mt][0] = __float_as_uint(p0.y);
                ahi[mt][1] = __float_as_uint(p1.x); alo[mt][1] = __float_as_uint(p1.y);
                ahi[mt][2] = __float_as_uint(p2.x); alo[mt][2] = __float_as_uint(p2.y);
                ahi[mt][3] = __float_as_uint(p3.x); alo[mt][3] = __float_as_uint(p3.y);
            }
#pragma unroll
            for (int nt = 0; nt < NT; nt++) {
                const int x = xb + nt * 8 + lq;
                const float* bp = &ins[(lr * 3 + (yl + 1 - a)) * ISTR + x + 1 - c];
                float rb0 = bp[0], rb1 = bp[4 * 3 * ISTR];
                unsigned bh0, bl0, bh1, bl1;
                tf32split(rb0, bh0, bl0);
                tf32split(rb1, bh1, bl1);
#pragma unroll
                for (int mt = 0; mt < 4; mt++) {
                    mma8(acc[mt][nt], ahi[mt], bh0, bh1);
                    mma8(acc[mt][nt], ahi[mt], bl0, bl1);
                    mma8(acc[mt][nt], alo[mt], bh0, bh1);
                }
            }
        }
        __syncthreads();
    }

    const int HOUT = 2 * HIN;
    const int oy = 2 * (y0 + yl) + py;
#pragma unroll
    for (int mt = 0; mt < 4; mt++) {
        const int oc = ocb + wm * 64 + mt * 16 + lq;
        const float b0v = bias[oc], b1v = bias[oc + 8];
#pragma unroll
        for (int nt = 0; nt < NT; nt++) {
            const int x = xb + nt * 8 + 2 * lr;
            const int ox = 2 * x + px;
            float* o0 = out + (((size_t)b * Cout + oc) * HOUT + oy) * HOUT + ox;
            float* o1 = o0 + (size_t)8 * HOUT * HOUT;
            o0[0] = fmaxf(acc[mt][nt][0] + b0v, 0.f);
            o0[2] = fmaxf(acc[mt][nt][1] + b0v, 0.f);
            o1[0] = fmaxf(acc[mt][nt][2] + b1v, 0.f);
            o1[2] = fmaxf(acc[mt][nt][3] + b1v, 0.f);
        }
    }
}

// ============================================================================
// Scalar kernels: conv1, dconv3out, vqk (proven R1 versions).
// ============================================================================
template <int CIN, bool RELU>
__global__ __launch_bounds__(256, 2)
void conv4s2(const float* __restrict__ in, const float* __restrict__ wt,
             const float* __restrict__ bias, float* __restrict__ out,
             int Cout, int Hin, int Win, int Hout, int Wout, int tilesX) {
    __shared__ float ish[34 * 36];
    __shared__ float wsh[64 * 16];

    const int tile = blockIdx.x;
    const int tx0 = (tile % tilesX) * 16;
    const int ty0 = (tile / tilesX) * 16;
    const int ocb = blockIdx.y * 64;
    const int b   = blockIdx.z;

    const int tid = threadIdx.x;
    const int og  = tid >> 5;
    const int sp  = tid & 31;
    const int r   = sp >> 1;
    const int cb  = (sp & 1) * 8;

    float acc[8][8];
#pragma unroll
    for (int o = 0; o < 8; o++) {
        float bv = bias[ocb + og * 8 + o];
#pragma unroll
        for (int j = 0; j < 8; j++) acc[o][j] = bv;
    }

    const int iy0 = ty0 * 2 - 1, ix0 = tx0 * 2 - 1;
    const float* inB = in + ((size_t)b * CIN) * Hin * Win;

    for (int ic = 0; ic < CIN; ic++) {
        const float* inC = inB + (size_t)ic * Hin * Win;
        for (int idx = tid; idx < 34 * 34; idx += 256) {
            int py = idx / 34, px = idx - py * 34;
            int iy = iy0 + py, ix = ix0 + px;
            float v = 0.f;
            if ((unsigned)iy < (unsigned)Hin && (unsigned)ix < (unsigned)Win)
                v = inC[iy * Win + ix];
            ish[py * 36 + px] = v;
        }
        const float* wC = wt + (ic * Cout + ocb) * 16;
        for (int idx = tid; idx < 1024; idx += 256) wsh[idx] = wC[idx];
        __syncthreads();

#pragma unroll
        for (int ky = 0; ky < 4; ky++) {
            const float* rp = &ish[(2 * r + ky) * 36 + 2 * cb];
            float4 v0 = *(const float4*)(rp);
            float4 v1 = *(const float4*)(rp + 4);
            float4 v2 = *(const float4*)(rp + 8);
            float4 v3 = *(const float4*)(rp + 12);
            float4 v4 = *(const float4*)(rp + 16);
            float riv[20] = {v0.x, v0.y, v0.z, v0.w, v1.x, v1.y, v1.z, v1.w,
                             v2.x, v2.y, v2.z, v2.w, v3.x, v3.y, v3.z, v3.w,
                             v4.x, v4.y, v4.z, v4.w};
#pragma unroll
            for (int kx = 0; kx < 4; kx++) {
                const int t = ky * 4 + kx;
                float wv[8];
#pragma unroll
                for (int o = 0; o < 8; o++) wv[o] = wsh[(og * 8 + o) * 16 + t];
#pragma unroll
                for (int o = 0; o < 8; o++)
#pragma unroll
                    for (int j = 0; j < 8; j++)
                        acc[o][j] = fmaf(wv[o], riv[kx + 2 * j], acc[o][j]);
            }
        }
        __syncthreads();
    }

    const int oy = ty0 + r;
    const int oxb = tx0 + cb;
#pragma unroll
    for (int o = 0; o < 8; o++) {
        float* op = out + (((size_t)b * Cout + ocb + og * 8 + o) * Hout + oy) * Wout + oxb;
        float tmp[8];
#pragma unroll
        for (int j = 0; j < 8; j++)
            tmp[j] = RELU ? fmaxf(acc[o][j], 0.f) : acc[o][j];
        *(float4*)op       = make_float4(tmp[0], tmp[1], tmp[2], tmp[3]);
        *(float4*)(op + 4) = make_float4(tmp[4], tmp[5], tmp[6], tmp[7]);
    }
}

__global__ __launch_bounds__(128, 4)
void dconv3out(const float* __restrict__ in, const float* __restrict__ wt,
               const float* __restrict__ bias, float* __restrict__ out,
               int tilesX) {
    const int Cin = 128, Hin = 128, Win = 128, Hout = 256, Wout = 256;
    __shared__ float ish[4][18 * 19];
    __shared__ float wsh[4][3 * 16];

    const int tile = blockIdx.x;
    const int ox0 = (tile % tilesX) * 32;
    const int oy0 = (tile / tilesX) * 32;
    const int b   = blockIdx.y;

    const int tid = threadIdx.x;
    const int q   = tid >> 5;
    const int py  = q >> 1, px = q & 1;
    const int sp  = tid & 31;
    const int ry  = sp >> 1;
    const int ch  = (sp & 1) * 8;

    float acc[3][8];
#pragma unroll
    for (int o = 0; o < 3; o++) {
        float bv = bias[o];
#pragma unroll
        for (int j = 0; j < 8; j++) acc[o][j] = bv;
    }

    const int iy0 = oy0 >> 1, ix0 = ox0 >> 1;
    const int kp = 1 - py, kq = 1 - px;

    for (int ic0 = 0; ic0 < Cin; ic0 += 4) {
        for (int idx = tid; idx < 4 * 324; idx += 128) {
            int icc = idx / 324, p = idx - icc * 324;
            int piy = p / 18, pix = p - piy * 18;
            int iy = iy0 - 1 + piy, ix = ix0 - 1 + pix;
            float v = 0.f;
            if ((unsigned)iy < (unsigned)Hin && (unsigned)ix < (unsigned)Win)
                v = in[(((size_t)b * Cin + ic0 + icc) * Hin + iy) * Win + ix];
            ish[icc][piy * 19 + pix] = v;
        }
        for (int idx = tid; idx < 4 * 48; idx += 128) {
            int icc = idx / 48, rmd = idx - icc * 48;
            wsh[icc][rmd] = wt[(ic0 + icc) * 48 + rmd];
        }
        __syncthreads();

#pragma unroll
        for (int icc = 0; icc < 4; icc++) {
#pragma unroll
            for (int a = 0; a < 2; a++) {
                const int ky  = kp + 2 * a;
                const int liy = ry + 1 + py - a;
                float iv[10];
                const int base = liy * 19 + ch + px;
#pragma unroll
                for (int j = 0; j < 10; j++) iv[j] = ish[icc][base + j];
#pragma unroll
                for (int c = 0; c < 2; c++) {
                    const int kx  = kq + 2 * c;
                    const int t   = ky * 4 + kx;
                    const int off = 1 - c;
                    float wv[3];
#pragma unroll
                    for (int o = 0; o < 3; o++) wv[o] = wsh[icc][o * 16 + t];
#pragma unroll
                    for (int o = 0; o < 3; o++)
#pragma unroll
                        for (int j = 0; j < 8; j++)
                            acc[o][j] = fmaf(wv[o], iv[j + off], acc[o][j]);
                }
            }
        }
        __syncthreads();
    }

    const int oy = oy0 + 2 * ry + py;
#pragma unroll
    for (int o = 0; o < 3; o++) {
        float* op = out + (((size_t)b * 3 + o) * Hout + oy) * Wout + ox0 + px + 2 * ch;
#pragma unroll
        for (int j = 0; j < 8; j++) op[2 * j] = acc[o][j];
    }
}

__global__ __launch_bounds__(128, 8)
void vqk(const float* __restrict__ ze, const float* __restrict__ emb,
         float* __restrict__ zq, float* __restrict__ idxf) {
    __shared__ __align__(16) float esh[64 * 64];
    __shared__ float en[64];

    const int row = blockIdx.x * 128 + threadIdx.x;
    float f[64];
    const float4* fp = (const float4*)(ze + (size_t)row * 64);
#pragma unroll
    for (int i = 0; i < 16; i++) {
        float4 v = fp[i];
        f[4 * i] = v.x; f[4 * i + 1] = v.y; f[4 * i + 2] = v.z; f[4 * i + 3] = v.w;
    }
    float fn = 0.f;
#pragma unroll
    for (int d = 0; d < 64; d++) fn = fmaf(f[d], f[d], fn);

    float best = 3.4e38f;
    int bidx = 0;
    for (int cb = 0; cb < 512; cb += 64) {
        __syncthreads();
        const float4* src = (const float4*)(emb + (size_t)cb * 64);
        for (int i = threadIdx.x; i < 1024; i += 128)
            ((float4*)esh)[i] = src[i];
        __syncthreads();
        if (threadIdx.x < 64) {
            float s = 0.f;
            const float* e = esh + threadIdx.x * 64;
#pragma unroll
            for (int d = 0; d < 64; d++) s = fmaf(e[d], e[d], s);
            en[threadIdx.x] = s;
        }
        __syncthreads();
        for (int c = 0; c < 64; c++) {
            const float4* ev = (const float4*)(esh + c * 64);
            float dot = 0.f;
#pragma unroll
            for (int i = 0; i < 16; i++) {
                float4 e = ev[i];
                dot = fmaf(f[4 * i], e.x, dot);
                dot = fmaf(f[4 * i + 1], e.y, dot);
                dot = fmaf(f[4 * i + 2], e.z, dot);
                dot = fmaf(f[4 * i + 3], e.w, dot);
            }
            float sc = fn - 2.f * dot + en[c];
            if (sc < best) { best = sc; bidx = cb + c; }
        }
    }

    idxf[row] = (float)bidx;
    const float4* ep = (const float4*)(emb + (size_t)bidx * 64);
    float4* qp = (float4*)(zq + (size_t)row * 64);
#pragma unroll
    for (int i = 0; i < 16; i++) qp[i] = ep[i];
}

// ---------------------------------------------------------------------------
extern "C" void kernel_launch(void* const* d_in, const int* in_sizes, int n_in,
                              void* d_out, int out_size) {
    (void)in_sizes; (void)n_in;
    const float* x   = (const float*)d_in[0];
    const float* w1  = (const float*)d_in[1];
    const float* b1  = (const float*)d_in[2];
    const float* w2  = (const float*)d_in[3];
    const float* b2  = (const float*)d_in[4];
    const float* w3  = (const float*)d_in[5];
    const float* b3  = (const float*)d_in[6];
    const float* d1w = (const float*)d_in[7];
    const float* d1b = (const float*)d_in[8];
    const float* d2w = (const float*)d_in[9];
    const float* d2b = (const float*)d_in[10];
    const float* d3w = (const float*)d_in[11];
    const float* d3b = (const float*)d_in[12];
    const float* emb = (const float*)d_in[13];

    float *h1, *h2, *g1, *g2, *ze, *zq, *idxf, *wt1;
    float2 *w2s, *d2s, *d1s, *w3s;
    cudaGetSymbolAddress((void**)&h1, g_h1);
    cudaGetSymbolAddress((void**)&h2, g_h2);
    cudaGetSymbolAddress((void**)&g1, g_g1);
    cudaGetSymbolAddress((void**)&g2, g_g2);
    cudaGetSymbolAddress((void**)&ze, g_ze);
    cudaGetSymbolAddress((void**)&zq, g_zq);
    cudaGetSymbolAddress((void**)&idxf, g_if);
    cudaGetSymbolAddress((void**)&wt1, g_wt1);
    cudaGetSymbolAddress((void**)&w2s, g_w2s);
    cudaGetSymbolAddress((void**)&d2s, g_d2s);
    cudaGetSymbolAddress((void**)&d1s, g_d1s);
    cudaGetSymbolAddress((void**)&w3s, g_w3s);

    float* outF = (float*)d_out;
    const int NX = NBATCH * 3 * 256 * 256;
    const int NZ = NBATCH * 64 * 32 * 32;
    const int NI = 16384;
    if (out_size >= NX + 2 * NZ + NI) {
        ze   = outF + NX;
        zq   = outF + NX + NZ;
        idxf = outF + NX + 2 * NZ;
    }

    static bool attr_done = false;
    if (!attr_done) {
        cudaFuncSetAttribute(conv2_mma, cudaFuncAttributeMaxDynamicSharedMemorySize,
                             (2 * C2_WS2 + C2_INS) * 4);
        cudaFuncSetAttribute(conv3_mma, cudaFuncAttributeMaxDynamicSharedMemorySize,
                             (2 * C3_WS2 + C3_INS) * 4);
        attr_done = true;
    }

    // 1-2: weight transforms needed for launches 3-4
    wsplit2t<<<2048, 256>>>(w2, w2s);
    wtrans<<<(128 * 3 * 16 + 255) / 256, 256>>>(w1, wt1, 128, 3);
    // 3: conv1
    conv4s2<3, true><<<dim3(64, 2, NBATCH), 256>>>(x, wt1, b1, h1, 128, 256, 256, 128, 128, 8);
    // 4: conv2  (this launch gets profiled)
    conv2_mma<<<dim3(32, 2, NBATCH), 256, (2 * C2_WS2 + C2_INS) * 4>>>(h1, w2s, b2, h2);
    // conv3 (K-slab x4 into g2) + reduce
    wsplit3<<<1024, 256>>>(w3, w3s);
    conv3_mma<<<dim3(4, 1, NBATCH * 4), 256, (2 * C3_WS2 + C3_INS) * 4>>>(h2, w3s, g2);
    addparts<<<NZ / 256, 256>>>(g2, b3, ze);
    // quantize
    vqk<<<128, 128>>>(ze, emb, zq, idxf);
    // decoder
    wsplitD1<<<1024, 256>>>(d1w, d1s);
    dconv_mma<64, 32><<<dim3(16, 4, NBATCH * 2), 256>>>(zq, d1s, d1b, g1, 256, 2);
    wsplitD2<<<2048, 256>>>(d2w, d2s);
    dconv_mma<256, 64><<<dim3(32, 4, NBATCH), 256>>>(g1, d2s, d2b, g2, 128, 1);
    dconv3out<<<dim3(64, NBATCH), 128>>>(g2, d3w, d3b, outF, 8);
}

// round 5
// speedup vs baseline: 2.0578x; 1.1827x over previous
#include <cuda_runtime.h>

// ---------------------------------------------------------------------------
// VQ-VAE forward, sm_100a.
//   Encoder conv2/conv3: mma.sync tf32, 3-term hi/lo split (argmin-safe).
//   Decoder dconv1/dconv2: mma.sync tf32, 1-term (x_recon tolerance ~1e-3).
//   conv1 / dconv3 / VQ: scalar-FFMA register-tiled.
// Output layout: [x_recon | z_e | z_q | idx(as float)], fp32.
// ---------------------------------------------------------------------------

#define NBATCH 16

// -------- scratch ------------------------------------------------------------
__device__ float g_h1[NBATCH * 128 * 128 * 128];
__device__ float g_h2[NBATCH * 256 * 64 * 64];
__device__ float g_g1[NBATCH * 256 * 64 * 64];
__device__ float g_g2[NBATCH * 128 * 128 * 128];
__device__ float g_ze[NBATCH * 64 * 32 * 32];
__device__ float g_zq[NBATCH * 64 * 32 * 32];
__device__ float g_if[16384];
__device__ float g_wt1[128 * 3 * 16];
__device__ float2 g_w2s[16 * 128 * 256];   // conv2  [t][ic][oc] (hi,lo)
__device__ float2 g_d2s[16 * 256 * 128];   // dconv2 [t][ic][oc]
__device__ float2 g_d1s[16 * 64 * 256];    // dconv1 [t][ic][oc]
__device__ float2 g_w3s[16 * 256 * 64];    // conv3  [t][ic][oc]

// -------- mma helpers --------------------------------------------------------
__device__ __forceinline__ void tf32split(float v, unsigned& hi, unsigned& lo) {
    unsigned h;
    asm("cvt.rna.tf32.f32 %0,%1;" : "=r"(h) : "f"(v));
    float l = v - __uint_as_float(h);
    unsigned lw;
    asm("cvt.rna.tf32.f32 %0,%1;" : "=r"(lw) : "f"(l));
    hi = h; lo = lw;
}
__device__ __forceinline__ unsigned tf32cvt(float v) {
    unsigned h;
    asm("cvt.rna.tf32.f32 %0,%1;" : "=r"(h) : "f"(v));
    return h;
}
__device__ __forceinline__ float2 splitpack(float v) {
    unsigned h, l;
    tf32split(v, h, l);
    return make_float2(__uint_as_float(h), __uint_as_float(l));
}
__device__ __forceinline__ void mma8(float* c, const unsigned* a,
                                     unsigned b0, unsigned b1) {
    asm("mma.sync.aligned.m16n8k8.row.col.f32.tf32.tf32.f32 "
        "{%0,%1,%2,%3},{%4,%5,%6,%7},{%8,%9},{%0,%1,%2,%3};"
        : "+f"(c[0]), "+f"(c[1]), "+f"(c[2]), "+f"(c[3])
        : "r"(a[0]), "r"(a[1]), "r"(a[2]), "r"(a[3]), "r"(b0), "r"(b1));
}

// -------- weight transforms --------------------------------------------------
__global__ void wtrans(const float* __restrict__ w, float* __restrict__ wo,
                       int Cout, int Cin) {   // OIHW -> [ic][oc][t]
    int idx = blockIdx.x * 256 + threadIdx.x;
    int total = Cout * Cin * 16;
    if (idx < total) {
        int t = idx & 15;
        int rest = idx >> 4;
        int ic = rest % Cin;
        int oc = rest / Cin;
        wo[(ic * Cout + oc) * 16 + t] = w[idx];
    }
}
__global__ void wsplit2t(const float* __restrict__ w, float2* __restrict__ wo) {
    int idx = blockIdx.x * 256 + threadIdx.x;   // 524288
    int t = idx & 15, ic = (idx >> 4) & 127, oc = idx >> 11;
    wo[(t * 128 + ic) * 256 + oc] = splitpack(w[idx]);
}
__global__ void wsplitD2(const float* __restrict__ w, float2* __restrict__ wo) {
    int idx = blockIdx.x * 256 + threadIdx.x;   // 524288
    int t = idx & 15, oc = (idx >> 4) & 127, ic = idx >> 11;
    wo[(t * 256 + ic) * 128 + oc] = splitpack(w[idx]);
}
__global__ void wsplitD1(const float* __restrict__ w, float2* __restrict__ wo) {
    int idx = blockIdx.x * 256 + threadIdx.x;   // 262144
    int t = idx & 15, oc = (idx >> 4) & 255, ic = idx >> 12;
    wo[(t * 64 + ic) * 256 + oc] = splitpack(w[idx]);
}
__global__ void wsplit3(const float* __restrict__ w, float2* __restrict__ wo) {
    int idx = blockIdx.x * 256 + threadIdx.x;   // 262144
    int t = idx & 15, ic = (idx >> 4) & 255, oc = idx >> 12;
    wo[(t * 256 + ic) * 64 + oc] = splitpack(w[idx]);
}

// ============================================================================
// conv2 MMA (3-term): h1 -> h2, k4 s2 p1, relu.
// ============================================================================
#define C2_WS2 (4 * 8 * 132)
#define C2_INS (8 * 6 * 132)
__global__ __launch_bounds__(256, 2)
void conv2_mma(const float* __restrict__ in, const float2* __restrict__ wt,
               const float* __restrict__ bias, float* __restrict__ out) {
    extern __shared__ float sm[];
    float2* ws = (float2*)sm;
    float* ins = sm + 2 * C2_WS2;

    const int oy0 = blockIdx.x * 2;
    const int ocb = blockIdx.y * 128;
    const int b   = blockIdx.z;

    const int tid  = threadIdx.x;
    const int wid  = tid >> 5;
    const int lane = tid & 31;
    const int wm   = wid >> 2;
    const int wn   = wid & 3;
    const int oyl  = wn >> 1;
    const int xb   = (wn & 1) * 32;
    const int lq   = lane >> 2;
    const int lr   = lane & 3;

    float acc[4][4][4];
#pragma unroll
    for (int mt = 0; mt < 4; mt++)
#pragma unroll
        for (int nt = 0; nt < 4; nt++)
#pragma unroll
            for (int i = 0; i < 4; i++) acc[mt][nt][i] = 0.f;

    const int iy0 = oy0 * 2 - 1;
    const float* inB = in + ((size_t)b * 128) * 128 * 128;

    for (int ch = 0; ch < 16; ch++) {
        for (int idx = tid; idx < 8 * 6 * 132; idx += 256) {
            int icl = idx / 792;
            int rem = idx - icl * 792;
            int r = rem / 132, c = rem - r * 132;
            int iy = iy0 + r, ix = c - 1;
            float v = 0.f;
            if ((unsigned)iy < 128u && (unsigned)ix < 128u)
                v = inB[((size_t)(ch * 8 + icl) * 128 + iy) * 128 + ix];
            ins[idx] = v;
        }
        for (int tg = 0; tg < 4; tg++) {
            for (int idx = tid; idx < 4096; idx += 256) {
                int oc = idx & 127;
                int icl = (idx >> 7) & 7;
                int tl = idx >> 10;
                ws[(tl * 8 + icl) * 132 + oc] =
                    wt[((size_t)((tg * 4 + tl) * 128 + ch * 8 + icl)) * 256 + ocb + oc];
            }
            __syncthreads();

#pragma unroll
            for (int tapl = 0; tapl < 4; tapl++) {
                const int ky = tg, kx = tapl;
                unsigned ahi[4][4], alo[4][4];
#pragma unroll
                for (int mt = 0; mt < 4; mt++) {
                    const float2* ap = &ws[(tapl * 8 + lr) * 132 + wm * 64 + mt * 16 + lq];
                    float2 p0 = ap[0], p1 = ap[8], p2 = ap[4 * 132], p3 = ap[4 * 132 + 8];
                    ahi[mt][0] = __float_as_uint(p0.x); alo[mt][0] = __float_as_uint(p0.y);
                    ahi[mt][1] = __float_as_uint(p1.x); alo[mt][1] = __float_as_uint(p1.y);
                    ahi[mt][2] = __float_as_uint(p2.x); alo[mt][2] = __float_as_uint(p2.y);
                    ahi[mt][3] = __float_as_uint(p3.x); alo[mt][3] = __float_as_uint(p3.y);
                }
#pragma unroll
                for (int nt = 0; nt < 4; nt++) {
                    const int ox = xb + nt * 8 + lq;
                    const float* bp = &ins[lr * 792 + (2 * oyl + ky) * 132 + 2 * ox + kx];
                    float rb0 = bp[0], rb1 = bp[4 * 792];
                    unsigned bh0, bl0, bh1, bl1;
                    tf32split(rb0, bh0, bl0);
                    tf32split(rb1, bh1, bl1);
#pragma unroll
                    for (int mt = 0; mt < 4; mt++) {
                        mma8(acc[mt][nt], ahi[mt], bh0, bh1);
                        mma8(acc[mt][nt], ahi[mt], bl0, bl1);
                        mma8(acc[mt][nt], alo[mt], bh0, bh1);
                    }
                }
            }
            __syncthreads();
        }
    }

    const int oy = oy0 + oyl;
#pragma unroll
    for (int mt = 0; mt < 4; mt++) {
        const int oc = ocb + wm * 64 + mt * 16 + lq;
        const float b0v = bias[oc], b1v = bias[oc + 8];
#pragma unroll
        for (int nt = 0; nt < 4; nt++) {
            const int ox = xb + nt * 8 + 2 * lr;
            float* o0 = out + (((size_t)b * 256 + oc) * 64 + oy) * 64 + ox;
            float* o1 = o0 + (size_t)8 * 64 * 64;
            *(float2*)o0 = make_float2(fmaxf(acc[mt][nt][0] + b0v, 0.f),
                                       fmaxf(acc[mt][nt][1] + b0v, 0.f));
            *(float2*)o1 = make_float2(fmaxf(acc[mt][nt][2] + b1v, 0.f),
                                       fmaxf(acc[mt][nt][3] + b1v, 0.f));
        }
    }
}

// ============================================================================
// conv3 MMA (3-term): h2 -> 4 K-slab partials.
// ============================================================================
#define C3_WS2 (4 * 8 * 68)
#define C3_INS (8 * 18 * 68)
__global__ __launch_bounds__(256, 2)
void conv3_mma(const float* __restrict__ in, const float2* __restrict__ wt,
               float* __restrict__ outp) {
    extern __shared__ float sm[];
    float2* ws = (float2*)sm;
    float* ins = sm + 2 * C3_WS2;

    const int r0   = blockIdx.x * 8;
    const int b    = blockIdx.z >> 2;
    const int slab = blockIdx.z & 3;

    const int tid  = threadIdx.x;
    const int w    = tid >> 5;
    const int lane = tid & 31;
    const int lq   = lane >> 2;
    const int lr   = lane & 3;

    float acc[4][4][4];
#pragma unroll
    for (int mt = 0; mt < 4; mt++)
#pragma unroll
        for (int nt = 0; nt < 4; nt++)
#pragma unroll
            for (int i = 0; i < 4; i++) acc[mt][nt][i] = 0.f;

    const int iy0 = r0 * 2 - 1;
    const float* inB = in + ((size_t)b * 256 + slab * 64) * 64 * 64;

    for (int ch = 0; ch < 8; ch++) {
        for (int idx = tid; idx < 8 * 18 * 66; idx += 256) {
            int icl = idx / 1188;
            int rem = idx - icl * 1188;
            int r = rem / 66, c = rem - r * 66;
            int iy = iy0 + r, ix = c - 1;
            float v = 0.f;
            if ((unsigned)iy < 64u && (unsigned)ix < 64u)
                v = inB[((size_t)(ch * 8 + icl) * 64 + iy) * 64 + ix];
            ins[icl * 1224 + r * 68 + c] = v;
        }
        for (int tg = 0; tg < 4; tg++) {
            for (int idx = tid; idx < 2048; idx += 256) {
                int oc = idx & 63;
                int icl = (idx >> 6) & 7;
                int tl = idx >> 9;
                ws[(tl * 8 + icl) * 68 + oc] =
                    wt[((size_t)((tg * 4 + tl) * 256 + slab * 64 + ch * 8 + icl)) * 64 + oc];
            }
            __syncthreads();

#pragma unroll
            for (int tapl = 0; tapl < 4; tapl++) {
                const int ky = tg, kx = tapl;
                unsigned ahi[4][4], alo[4][4];
#pragma unroll
                for (int mt = 0; mt < 4; mt++) {
                    const float2* ap = &ws[(tapl * 8 + lr) * 68 + mt * 16 + lq];
                    float2 p0 = ap[0], p1 = ap[8], p2 = ap[4 * 68], p3 = ap[4 * 68 + 8];
                    ahi[mt][0] = __float_as_uint(p0.x); alo[mt][0] = __float_as_uint(p0.y);
                    ahi[mt][1] = __float_as_uint(p1.x); alo[mt][1] = __float_as_uint(p1.y);
                    ahi[mt][2] = __float_as_uint(p2.x); alo[mt][2] = __float_as_uint(p2.y);
                    ahi[mt][3] = __float_as_uint(p3.x); alo[mt][3] = __float_as_uint(p3.y);
                }
#pragma unroll
                for (int nt = 0; nt < 4; nt++) {
                    const int col = nt * 8 + lq;
                    const float* bp = &ins[lr * 1224 + (2 * w + ky) * 68 + 2 * col + kx];
                    float rb0 = bp[0], rb1 = bp[4 * 1224];
                    unsigned bh0, bl0, bh1, bl1;
                    tf32split(rb0, bh0, bl0);
                    tf32split(rb1, bh1, bl1);
#pragma unroll
                    for (int mt = 0; mt < 4; mt++) {
                        mma8(acc[mt][nt], ahi[mt], bh0, bh1);
                        mma8(acc[mt][nt], ahi[mt], bl0, bl1);
                        mma8(acc[mt][nt], alo[mt], bh0, bh1);
                    }
                }
            }
            __syncthreads();
        }
    }

    const int NZ = NBATCH * 64 * 32 * 32;
    float* part = outp + (size_t)slab * NZ;
    const int row = r0 + w;
#pragma unroll
    for (int mt = 0; mt < 4; mt++) {
        const int oc = mt * 16 + lq;
#pragma unroll
        for (int nt = 0; nt < 4; nt++) {
            float* o0 = part + (((size_t)b * 64 + oc) * 32 + row) * 32 + nt * 8 + 2 * lr;
            float* o1 = o0 + (size_t)8 * 32 * 32;
            *(float2*)o0 = make_float2(acc[mt][nt][0], acc[mt][nt][1]);
            *(float2*)o1 = make_float2(acc[mt][nt][2], acc[mt][nt][3]);
        }
    }
}

__global__ void addparts(const float* __restrict__ p, const float* __restrict__ bias,
                         float* __restrict__ ze) {
    const int S = NBATCH * 64 * 32 * 32;
    int i = blockIdx.x * 256 + threadIdx.x;
    float v = p[i] + p[i + S] + p[i + 2 * S] + p[i + 3 * S];
    ze[i] = v + bias[(i >> 10) & 63];
}

// ============================================================================
// dconv MMA (TERMS = 3: exact-ish split; TERMS = 1: plain tf32, 3x less work)
// ============================================================================
template <int CIN, int HIN, int TERMS>
__global__ __launch_bounds__(256, 2)
void dconv_mma(const float* __restrict__ in, const float2* __restrict__ wt,
               const float* __restrict__ bias, float* __restrict__ out,
               int Cout, int nOcb) {
    const int WROW = HIN + 2;
    __shared__ float2 ws[4 * 8 * 132];
    __shared__ float ins[8 * 3 * (HIN + 4)];

    const int y0 = blockIdx.x * 2;
    const int py = blockIdx.y >> 1, px = blockIdx.y & 1;
    const int b   = blockIdx.z / nOcb;
    const int ocb = (blockIdx.z % nOcb) * 128;

    const int tid  = threadIdx.x;
    const int wid  = tid >> 5;
    const int lane = tid & 31;
    const int wm   = wid >> 2;
    const int wn   = wid & 3;
    const int yl   = wn >> 1;
    const int xb   = (wn & 1) * (HIN / 2);
    const int lq   = lane >> 2;
    const int lr   = lane & 3;
    const int NT   = HIN / 16;
    const int ISTR = HIN + 4;

    float acc[4][4][4];
#pragma unroll
    for (int mt = 0; mt < 4; mt++)
#pragma unroll
        for (int nt = 0; nt < 4; nt++)
#pragma unroll
            for (int i = 0; i < 4; i++) acc[mt][nt][i] = 0.f;

    const float* inB = in + ((size_t)b * CIN) * HIN * HIN;

    for (int ch = 0; ch < CIN / 8; ch++) {
        for (int idx = tid; idx < 8 * 3 * WROW; idx += 256) {
            int icl = idx / (3 * WROW);
            int rem = idx - icl * 3 * WROW;
            int r = rem / WROW, s = rem - r * WROW;
            int iy = y0 + py - 1 + r;
            int ix = px - 1 + s;
            float v = 0.f;
            if ((unsigned)iy < (unsigned)HIN && (unsigned)ix < (unsigned)HIN)
                v = inB[((size_t)(ch * 8 + icl) * HIN + iy) * HIN + ix];
            ins[(icl * 3 + r) * ISTR + s] = v;
        }
        for (int idx = tid; idx < 4096; idx += 256) {
            int oc = idx & 127;
            int icl = (idx >> 7) & 7;
            int tl = idx >> 10;
            int a = tl >> 1, c = tl & 1;
            int t = (1 - py + 2 * a) * 4 + (1 - px + 2 * c);
            ws[(tl * 8 + icl) * 132 + oc] =
                wt[((size_t)(t * CIN + ch * 8 + icl)) * Cout + ocb + oc];
        }
        __syncthreads();

#pragma unroll
        for (int tl = 0; tl < 4; tl++) {
            const int a = tl >> 1, c = tl & 1;
            unsigned ahi[4][4], alo[4][4];
#pragma unroll
            for (int mt = 0; mt < 4; mt++) {
                const float2* ap = &ws[(tl * 8 + lr) * 132 + wm * 64 + mt * 16 + lq];
                float2 p0 = ap[0], p1 = ap[8], p2 = ap[4 * 132], p3 = ap[4 * 132 + 8];
                ahi[mt][0] = __float_as_uint(p0.x);
                ahi[mt][1] = __float_as_uint(p1.x);
                ahi[mt][2] = __float_as_uint(p2.x);
                ahi[mt][3] = __float_as_uint(p3.x);
                if (TERMS == 3) {
                    alo[mt][0] = __float_as_uint(p0.y);
                    alo[mt][1] = __float_as_uint(p1.y);
                    alo[mt][2] = __float_as_uint(p2.y);
                    alo[mt][3] = __float_as_uint(p3.y);
                }
            }
#pragma unroll
            for (int nt = 0; nt < NT; nt++) {
                const int x = xb + nt * 8 + lq;
                const float* bp = &ins[(lr * 3 + (yl + 1 - a)) * ISTR + x + 1 - c];
                float rb0 = bp[0], rb1 = bp[4 * 3 * ISTR];
                if (TERMS == 3) {
                    unsigned bh0, bl0, bh1, bl1;
                    tf32split(rb0, bh0, bl0);
                    tf32split(rb1, bh1, bl1);
#pragma unroll
                    for (int mt = 0; mt < 4; mt++) {
                        mma8(acc[mt][nt], ahi[mt], bh0, bh1);
                        mma8(acc[mt][nt], ahi[mt], bl0, bl1);
                        mma8(acc[mt][nt], alo[mt], bh0, bh1);
                    }
                } else {
                    unsigned bh0 = tf32cvt(rb0), bh1 = tf32cvt(rb1);
#pragma unroll
                    for (int mt = 0; mt < 4; mt++)
                        mma8(acc[mt][nt], ahi[mt], bh0, bh1);
                }
            }
        }
        __syncthreads();
    }

    const int HOUT = 2 * HIN;
    const int oy = 2 * (y0 + yl) + py;
#pragma unroll
    for (int mt = 0; mt < 4; mt++) {
        const int oc = ocb + wm * 64 + mt * 16 + lq;
        const float b0v = bias[oc], b1v = bias[oc + 8];
#pragma unroll
        for (int nt = 0; nt < NT; nt++) {
            const int x = xb + nt * 8 + 2 * lr;
            const int ox = 2 * x + px;
            float* o0 = out + (((size_t)b * Cout + oc) * HOUT + oy) * HOUT + ox;
            float* o1 = o0 + (size_t)8 * HOUT * HOUT;
            o0[0] = fmaxf(acc[mt][nt][0] + b0v, 0.f);
            o0[2] = fmaxf(acc[mt][nt][1] + b0v, 0.f);
            o1[0] = fmaxf(acc[mt][nt][2] + b1v, 0.f);
            o1[2] = fmaxf(acc[mt][nt][3] + b1v, 0.f);
        }
    }
}

// ============================================================================
// Scalar kernels: conv1, dconv3out, vqk.
// ============================================================================
template <int CIN, bool RELU>
__global__ __launch_bounds__(256, 2)
void conv4s2(const float* __restrict__ in, const float* __restrict__ wt,
             const float* __restrict__ bias, float* __restrict__ out,
             int Cout, int Hin, int Win, int Hout, int Wout, int tilesX) {
    __shared__ float ish[34 * 36];
    __shared__ float wsh[64 * 16];

    const int tile = blockIdx.x;
    const int tx0 = (tile % tilesX) * 16;
    const int ty0 = (tile / tilesX) * 16;
    const int ocb = blockIdx.y * 64;
    const int b   = blockIdx.z;

    const int tid = threadIdx.x;
    const int og  = tid >> 5;
    const int sp  = tid & 31;
    const int r   = sp >> 1;
    const int cb  = (sp & 1) * 8;

    float acc[8][8];
#pragma unroll
    for (int o = 0; o < 8; o++) {
        float bv = bias[ocb + og * 8 + o];
#pragma unroll
        for (int j = 0; j < 8; j++) acc[o][j] = bv;
    }

    const int iy0 = ty0 * 2 - 1, ix0 = tx0 * 2 - 1;
    const float* inB = in + ((size_t)b * CIN) * Hin * Win;

    for (int ic = 0; ic < CIN; ic++) {
        const float* inC = inB + (size_t)ic * Hin * Win;
        for (int idx = tid; idx < 34 * 34; idx += 256) {
            int py = idx / 34, px = idx - py * 34;
            int iy = iy0 + py, ix = ix0 + px;
            float v = 0.f;
            if ((unsigned)iy < (unsigned)Hin && (unsigned)ix < (unsigned)Win)
                v = inC[iy * Win + ix];
            ish[py * 36 + px] = v;
        }
        const float* wC = wt + (ic * Cout + ocb) * 16;
        for (int idx = tid; idx < 1024; idx += 256) wsh[idx] = wC[idx];
        __syncthreads();

#pragma unroll
        for (int ky = 0; ky < 4; ky++) {
            const float* rp = &ish[(2 * r + ky) * 36 + 2 * cb];
            float4 v0 = *(const float4*)(rp);
            float4 v1 = *(const float4*)(rp + 4);
            float4 v2 = *(const float4*)(rp + 8);
            float4 v3 = *(const float4*)(rp + 12);
            float4 v4 = *(const float4*)(rp + 16);
            float riv[20] = {v0.x, v0.y, v0.z, v0.w, v1.x, v1.y, v1.z, v1.w,
                             v2.x, v2.y, v2.z, v2.w, v3.x, v3.y, v3.z, v3.w,
                             v4.x, v4.y, v4.z, v4.w};
#pragma unroll
            for (int kx = 0; kx < 4; kx++) {
                const int t = ky * 4 + kx;
                float wv[8];
#pragma unroll
                for (int o = 0; o < 8; o++) wv[o] = wsh[(og * 8 + o) * 16 + t];
#pragma unroll
                for (int o = 0; o < 8; o++)
#pragma unroll
                    for (int j = 0; j < 8; j++)
                        acc[o][j] = fmaf(wv[o], riv[kx + 2 * j], acc[o][j]);
            }
        }
        __syncthreads();
    }

    const int oy = ty0 + r;
    const int oxb = tx0 + cb;
#pragma unroll
    for (int o = 0; o < 8; o++) {
        float* op = out + (((size_t)b * Cout + ocb + og * 8 + o) * Hout + oy) * Wout + oxb;
        float tmp[8];
#pragma unroll
        for (int j = 0; j < 8; j++)
            tmp[j] = RELU ? fmaxf(acc[o][j], 0.f) : acc[o][j];
        *(float4*)op       = make_float4(tmp[0], tmp[1], tmp[2], tmp[3]);
        *(float4*)(op + 4) = make_float4(tmp[4], tmp[5], tmp[6], tmp[7]);
    }
}

__global__ __launch_bounds__(128, 4)
void dconv3out(const float* __restrict__ in, const float* __restrict__ wt,
               const float* __restrict__ bias, float* __restrict__ out,
               int tilesX) {
    const int Cin = 128, Hin = 128, Win = 128, Hout = 256, Wout = 256;
    __shared__ float ish[4][18 * 19];
    __shared__ float wsh[4][3 * 16];

    const int tile = blockIdx.x;
    const int ox0 = (tile % tilesX) * 32;
    const int oy0 = (tile / tilesX) * 32;
    const int b   = blockIdx.y;

    const int tid = threadIdx.x;
    const int q   = tid >> 5;
    const int py  = q >> 1, px = q & 1;
    const int sp  = tid & 31;
    const int ry  = sp >> 1;
    const int ch  = (sp & 1) * 8;

    float acc[3][8];
#pragma unroll
    for (int o = 0; o < 3; o++) {
        float bv = bias[o];
#pragma unroll
        for (int j = 0; j < 8; j++) acc[o][j] = bv;
    }

    const int iy0 = oy0 >> 1, ix0 = ox0 >> 1;
    const int kp = 1 - py, kq = 1 - px;

    for (int ic0 = 0; ic0 < Cin; ic0 += 4) {
        for (int idx = tid; idx < 4 * 324; idx += 128) {
            int icc = idx / 324, p = idx - icc * 324;
            int piy = p / 18, pix = p - piy * 18;
            int iy = iy0 - 1 + piy, ix = ix0 - 1 + pix;
            float v = 0.f;
            if ((unsigned)iy < (unsigned)Hin && (unsigned)ix < (unsigned)Win)
                v = in[(((size_t)b * Cin + ic0 + icc) * Hin + iy) * Win + ix];
            ish[icc][piy * 19 + pix] = v;
        }
        for (int idx = tid; idx < 4 * 48; idx += 128) {
            int icc = idx / 48, rmd = idx - icc * 48;
            wsh[icc][rmd] = wt[(ic0 + icc) * 48 + rmd];
        }
        __syncthreads();

#pragma unroll
        for (int icc = 0; icc < 4; icc++) {
#pragma unroll
            for (int a = 0; a < 2; a++) {
                const int ky  = kp + 2 * a;
                const int liy = ry + 1 + py - a;
                float iv[10];
                const int base = liy * 19 + ch + px;
#pragma unroll
                for (int j = 0; j < 10; j++) iv[j] = ish[icc][base + j];
#pragma unroll
                for (int c = 0; c < 2; c++) {
                    const int kx  = kq + 2 * c;
                    const int t   = ky * 4 + kx;
                    const int off = 1 - c;
                    float wv[3];
#pragma unroll
                    for (int o = 0; o < 3; o++) wv[o] = wsh[icc][o * 16 + t];
#pragma unroll
                    for (int o = 0; o < 3; o++)
#pragma unroll
                        for (int j = 0; j < 8; j++)
                            acc[o][j] = fmaf(wv[o], iv[j + off], acc[o][j]);
                }
            }
        }
        __syncthreads();
    }

    const int oy = oy0 + 2 * ry + py;
#pragma unroll
    for (int o = 0; o < 3; o++) {
        float* op = out + (((size_t)b * 3 + o) * Hout + oy) * Wout + ox0 + px + 2 * ch;
#pragma unroll
        for (int j = 0; j < 8; j++) op[2 * j] = acc[o][j];
    }
}

__global__ __launch_bounds__(128, 8)
void vqk(const float* __restrict__ ze, const float* __restrict__ emb,
         float* __restrict__ zq, float* __restrict__ idxf) {
    __shared__ __align__(16) float esh[64 * 64];
    __shared__ float en[64];

    const int row = blockIdx.x * 128 + threadIdx.x;
    float f[64];
    const float4* fp = (const float4*)(ze + (size_t)row * 64);
#pragma unroll
    for (int i = 0; i < 16; i++) {
        float4 v = fp[i];
        f[4 * i] = v.x; f[4 * i + 1] = v.y; f[4 * i + 2] = v.z; f[4 * i + 3] = v.w;
    }
    float fn = 0.f;
#pragma unroll
    for (int d = 0; d < 64; d++) fn = fmaf(f[d], f[d], fn);

    float best = 3.4e38f;
    int bidx = 0;
    for (int cb = 0; cb < 512; cb += 64) {
        __syncthreads();
        const float4* src = (const float4*)(emb + (size_t)cb * 64);
        for (int i = threadIdx.x; i < 1024; i += 128)
            ((float4*)esh)[i] = src[i];
        __syncthreads();
        if (threadIdx.x < 64) {
            float s = 0.f;
            const float* e = esh + threadIdx.x * 64;
#pragma unroll
            for (int d = 0; d < 64; d++) s = fmaf(e[d], e[d], s);
            en[threadIdx.x] = s;
        }
        __syncthreads();
        for (int c = 0; c < 64; c++) {
            const float4* ev = (const float4*)(esh + c * 64);
            float dot = 0.f;
#pragma unroll
            for (int i = 0; i < 16; i++) {
                float4 e = ev[i];
                dot = fmaf(f[4 * i], e.x, dot);
                dot = fmaf(f[4 * i + 1], e.y, dot);
                dot = fmaf(f[4 * i + 2], e.z, dot);
                dot = fmaf(f[4 * i + 3], e.w, dot);
            }
            float sc = fn - 2.f * dot + en[c];
            if (sc < best) { best = sc; bidx = cb + c; }
        }
    }

    idxf[row] = (float)bidx;
    const float4* ep = (const float4*)(emb + (size_t)bidx * 64);
    float4* qp = (float4*)(zq + (size_t)row * 64);
#pragma unroll
    for (int i = 0; i < 16; i++) qp[i] = ep[i];
}

// ---------------------------------------------------------------------------
extern "C" void kernel_launch(void* const* d_in, const int* in_sizes, int n_in,
                              void* d_out, int out_size) {
    (void)in_sizes; (void)n_in;
    const float* x   = (const float*)d_in[0];
    const float* w1  = (const float*)d_in[1];
    const float* b1  = (const float*)d_in[2];
    const float* w2  = (const float*)d_in[3];
    const float* b2  = (const float*)d_in[4];
    const float* w3  = (const float*)d_in[5];
    const float* b3  = (const float*)d_in[6];
    const float* d1w = (const float*)d_in[7];
    const float* d1b = (const float*)d_in[8];
    const float* d2w = (const float*)d_in[9];
    const float* d2b = (const float*)d_in[10];
    const float* d3w = (const float*)d_in[11];
    const float* d3b = (const float*)d_in[12];
    const float* emb = (const float*)d_in[13];

    float *h1, *h2, *g1, *g2, *ze, *zq, *idxf, *wt1;
    float2 *w2s, *d2s, *d1s, *w3s;
    cudaGetSymbolAddress((void**)&h1, g_h1);
    cudaGetSymbolAddress((void**)&h2, g_h2);
    cudaGetSymbolAddress((void**)&g1, g_g1);
    cudaGetSymbolAddress((void**)&g2, g_g2);
    cudaGetSymbolAddress((void**)&ze, g_ze);
    cudaGetSymbolAddress((void**)&zq, g_zq);
    cudaGetSymbolAddress((void**)&idxf, g_if);
    cudaGetSymbolAddress((void**)&wt1, g_wt1);
    cudaGetSymbolAddress((void**)&w2s, g_w2s);
    cudaGetSymbolAddress((void**)&d2s, g_d2s);
    cudaGetSymbolAddress((void**)&d1s, g_d1s);
    cudaGetSymbolAddress((void**)&w3s, g_w3s);

    float* outF = (float*)d_out;
    const int NX = NBATCH * 3 * 256 * 256;
    const int NZ = NBATCH * 64 * 32 * 32;
    const int NI = 16384;
    if (out_size >= NX + 2 * NZ + NI) {
        ze   = outF + NX;
        zq   = outF + NX + NZ;
        idxf = outF + NX + 2 * NZ;
    }

    static bool attr_done = false;
    if (!attr_done) {
        cudaFuncSetAttribute(conv2_mma, cudaFuncAttributeMaxDynamicSharedMemorySize,
                             (2 * C2_WS2 + C2_INS) * 4);
        cudaFuncSetAttribute(conv3_mma, cudaFuncAttributeMaxDynamicSharedMemorySize,
                             (2 * C3_WS2 + C3_INS) * 4);
        attr_done = true;
    }

    wsplit2t<<<2048, 256>>>(w2, w2s);
    wtrans<<<(128 * 3 * 16 + 255) / 256, 256>>>(w1, wt1, 128, 3);
    conv4s2<3, true><<<dim3(64, 2, NBATCH), 256>>>(x, wt1, b1, h1, 128, 256, 256, 128, 128, 8);
    conv2_mma<<<dim3(32, 2, NBATCH), 256, (2 * C2_WS2 + C2_INS) * 4>>>(h1, w2s, b2, h2);
    wsplit3<<<1024, 256>>>(w3, w3s);
    conv3_mma<<<dim3(4, 1, NBATCH * 4), 256, (2 * C3_WS2 + C3_INS) * 4>>>(h2, w3s, g2);
    addparts<<<NZ / 256, 256>>>(g2, b3, ze);
    vqk<<<128, 128>>>(ze, emb, zq, idxf);
    wsplitD1<<<1024, 256>>>(d1w, d1s);
    dconv_mma<64, 32, 1><<<dim3(16, 4, NBATCH * 2), 256>>>(zq, d1s, d1b, g1, 256, 2);
    wsplitD2<<<2048, 256>>>(d2w, d2s);
    dconv_mma<256, 64, 1><<<dim3(32, 4, NBATCH), 256>>>(g1, d2s, d2b, g2, 128, 1);
    dconv3out<<<dim3(64, NBATCH), 128>>>(g2, d3w, d3b, outF, 8);
}